// round 10
// baseline (speedup 1.0000x reference)
#include <cuda_runtime.h>
#include <math.h>

// ---------------- problem constants ----------------
#define Bc   4
#define Nc   50000
#define BNc  (Bc * Nc)
#define Tc   12
#define Hc   32
#define H2c  64
#define Rc   64

#define NRM     0.4204482076268573f   /* 32^-0.25 */
#define RATIO   0.125f                /* 64^-0.5  */
#define EPSP    1e-4f
#define EPS_LN  1e-5f

#define PB         391                /* kv partial blocks per batch */
#define CHUNK      128                /* nodes per kv block          */
#define TJ         32                 /* k tile in kv inner loop     */
#define NBLK       391                /* ceil(Nc/128)                */
#define DEN_CHUNKS 782                /* ceil(Nc/64)                 */

typedef unsigned long long u64;

// ---------------- f32x2 packed math (Blackwell) ----------------
__device__ __forceinline__ u64 pk2(float a, float b) {
    u64 r;
    asm("mov.b64 %0, {%1, %2};" : "=l"(r) : "f"(a), "f"(b));
    return r;
}
__device__ __forceinline__ void fma2(u64& d, u64 a, u64 b) {
    asm("fma.rn.f32x2 %0, %1, %2, %0;" : "+l"(d) : "l"(a), "l"(b));
}
__device__ __forceinline__ void upk2(float& lo, float& hi, u64 v) {
    asm("mov.b64 {%0, %1}, %2;" : "=f"(lo), "=f"(hi) : "l"(v));
}

// ---------------- scratch (row-major per-node layouts) ----------------
__device__ float    d_qp[Nc * Rc];        // [n][r]
__device__ float    d_fk[Nc * Rc];        // [n][r]
__device__ float    d_kp[Nc * Rc];        // [n][r]
__device__ float    d_hnode[Nc * H2c];    // [n][o]
__device__ float    d_h0[(size_t)BNc * H2c];  // [bn][c]
__device__ float    d_ie[(size_t)BNc * Hc];   // [bn][h]
__device__ unsigned d_keymax;
__device__ float    d_kv[Bc][Rc * H2c];
__device__ float    d_denv[Rc];
__device__ float    d_kvpart[Bc][PB][Rc * H2c];
__device__ float    d_denpart[Rc][DEN_CHUNKS];

__global__ void kInit() { d_keymax = 0u; }

__device__ __forceinline__ float decode_max(unsigned enc) {
    return (enc & 0x80000000u) ? __uint_as_float(enc ^ 0x80000000u)
                               : __uint_as_float(~enc);
}

// ---------------- Stage A: split y=0 queries (smem dd cache) | y=1 keys+hnode ----------------
__global__ void __launch_bounds__(128) kA(
    const float* __restrict__ node_emb,
    const float* __restrict__ w1, const float* __restrict__ b1,
    const float* __restrict__ w2, const float* __restrict__ b2,
    const float* __restrict__ rm1,
    const float* __restrict__ fc_w, const float* __restrict__ fc_b)
{
    __shared__ float sm[11424];
    int tid = threadIdx.x;
    int n = blockIdx.x * 128 + tid;

    if (blockIdx.y == 0) {
        // ---------- queries ----------
        float* s_w1 = sm;            // 1024
        float* s_rm = sm + 1024;     // 2048
        float* s_b1 = sm + 3072;     // 32
        float* s_dd = sm + 3104;     // 64*128 = 8192
        for (int i = tid; i < Hc * Hc; i += 128) s_w1[i] = w1[i];
        for (int i = tid; i < Rc * Hc; i += 128) s_rm[i] = rm1[i];
        if (tid < Hc) s_b1[tid] = b1[tid];
        __syncthreads();
        if (n >= Nc) return;

        float nd[Hc];
        #pragma unroll
        for (int d = 0; d < Hc; d++) nd[d] = node_emb[n * Hc + d];

        float nv[Hc];
        #pragma unroll
        for (int h = 0; h < Hc; h++) {
            float a = s_b1[h];
            #pragma unroll
            for (int d = 0; d < Hc; d++) a += nd[d] * s_w1[h * Hc + d];
            nv[h] = a;
        }
        float diag = 0.f;
        #pragma unroll
        for (int h = 0; h < Hc; h++) diag += nv[h] * nv[h];
        diag *= 0.5f * NRM * NRM;

        float mx = -3.0e38f;
        for (int r = 0; r < Rc; r++) {
            float a = 0.f;
            #pragma unroll
            for (int h = 0; h < Hc; h++) a += nv[h] * s_rm[r * Hc + h];
            a *= NRM;
            s_dd[r * 128 + tid] = a;
            mx = fmaxf(mx, a);
        }
        float base = diag + mx;
        for (int r4 = 0; r4 < 16; r4++) {
            float4 v;
            v.x = RATIO * (__expf(s_dd[(r4 * 4 + 0) * 128 + tid] - base) + EPSP);
            v.y = RATIO * (__expf(s_dd[(r4 * 4 + 1) * 128 + tid] - base) + EPSP);
            v.z = RATIO * (__expf(s_dd[(r4 * 4 + 2) * 128 + tid] - base) + EPSP);
            v.w = RATIO * (__expf(s_dd[(r4 * 4 + 3) * 128 + tid] - base) + EPSP);
            *(float4*)&d_qp[(size_t)n * Rc + r4 * 4] = v;
        }
    } else {
        // ---------- keys + hnode ----------
        float* s_w2 = sm;            // 1024
        float* s_rm = sm + 1024;     // 2048
        float* s_fr = sm + 3072;     // 2048
        float* s_b2 = sm + 5120;     // 32
        float* s_fb = sm + 5152;     // 64
        for (int i = tid; i < Hc * Hc; i += 128) s_w2[i] = w2[i];
        for (int i = tid; i < Rc * Hc; i += 128) s_rm[i] = rm1[i];
        for (int i = tid; i < H2c * Hc; i += 128) {
            int o = i / Hc, d = i % Hc;
            s_fr[i] = fc_w[o * H2c + Hc + d];
        }
        if (tid < Hc)  s_b2[tid] = b2[tid];
        if (tid < H2c) s_fb[tid] = fc_b[tid];
        __syncthreads();

        float kmaxdd = -3.0e38f;
        if (n < Nc) {
            float nd[Hc];
            #pragma unroll
            for (int d = 0; d < Hc; d++) nd[d] = node_emb[n * Hc + d];

            float nv[Hc];
            #pragma unroll
            for (int h = 0; h < Hc; h++) {
                float a = s_b2[h];
                #pragma unroll
                for (int d = 0; d < Hc; d++) a += nd[d] * s_w2[h * Hc + d];
                nv[h] = a;
            }
            float diagk = 0.f;
            #pragma unroll
            for (int h = 0; h < Hc; h++) diagk += nv[h] * nv[h];
            diagk *= 0.5f * NRM * NRM;

            for (int r4 = 0; r4 < 16; r4++) {
                float vv[4];
                #pragma unroll
                for (int q = 0; q < 4; q++) {
                    int r = r4 * 4 + q;
                    float a = 0.f;
                    #pragma unroll
                    for (int h = 0; h < Hc; h++) a += nv[h] * s_rm[r * Hc + h];
                    a *= NRM;
                    vv[q] = a - diagk;
                    kmaxdd = fmaxf(kmaxdd, a);
                }
                *(float4*)&d_fk[(size_t)n * Rc + r4 * 4] =
                    make_float4(vv[0], vv[1], vv[2], vv[3]);
            }

            for (int o4 = 0; o4 < 16; o4++) {
                float vv[4];
                #pragma unroll
                for (int q = 0; q < 4; q++) {
                    int o = o4 * 4 + q;
                    float a = s_fb[o];
                    #pragma unroll
                    for (int d = 0; d < Hc; d++) a += nd[d] * s_fr[o * Hc + d];
                    vv[q] = a;
                }
                *(float4*)&d_hnode[(size_t)n * H2c + o4 * 4] =
                    make_float4(vv[0], vv[1], vv[2], vv[3]);
            }
        }
        #pragma unroll
        for (int off = 16; off; off >>= 1)
            kmaxdd = fmaxf(kmaxdd, __shfl_xor_sync(0xffffffffu, kmaxdd, off));
        if ((tid & 31) == 0) {
            unsigned bits = __float_as_uint(kmaxdd);
            unsigned enc = (bits & 0x80000000u) ? ~bits : (bits | 0x80000000u);
            atomicMax(&d_keymax, enc);
        }
    }
}

// ---------------- kKP: kp = ratio*(exp(fk - M) + eps); den partials ----------------
// block = 256 threads: r = tid&63, ns = tid>>6; block covers 64 n.
__global__ void __launch_bounds__(256) kKP()
{
    int tid = threadIdx.x;
    int r = tid & 63;
    int ns = tid >> 6;
    int n0 = blockIdx.x * 64;
    float M = decode_max(d_keymax);

    float dreg = 0.f;
    #pragma unroll 4
    for (int i = 0; i < 16; i++) {
        int n = n0 + ns * 16 + i;
        if (n < Nc) {
            float v = RATIO * (__expf(d_fk[(size_t)n * Rc + r] - M) + EPSP);
            d_kp[(size_t)n * Rc + r] = v;
            dreg += v;
        }
    }
    __shared__ float s_red[4][64];
    s_red[ns][r] = dreg;
    __syncthreads();
    if (tid < 64) {
        float s = ((s_red[0][tid] + s_red[1][tid]) +
                   (s_red[2][tid] + s_red[3][tid]));
        d_denpart[tid][blockIdx.x] = s;
    }
}

// ---------------- Stage V: packed ie-GEMM + vectorized row I/O ----------------
__global__ void __launch_bounds__(128, 7) kV(
    const float* __restrict__ x,
    const float* __restrict__ w_input, const float* __restrict__ b_input,
    const float* __restrict__ fc_w)
{
    __shared__ u64   s_wiT[Tc * 16];          // w_input transposed, f32x2 pairs [t][hp]
    __shared__ float s_bi[Hc], s_fl[H2c * Hc];
    int tid = threadIdx.x;
    for (int i = tid; i < Tc * 16; i += 128) {
        int t = i >> 4, hp = i & 15;
        s_wiT[i] = pk2(w_input[(2 * hp) * Tc + t], w_input[(2 * hp + 1) * Tc + t]);
    }
    for (int i = tid; i < H2c * Hc; i += 128) {
        int o = i / Hc, d = i % Hc;
        s_fl[i] = fc_w[o * H2c + d];
    }
    if (tid < Hc) s_bi[tid] = b_input[tid];
    __syncthreads();

    int bn = blockIdx.x * 128 + tid;
    if (bn >= BNc) return;
    int n = bn % Nc;

    const float* xp = x + (size_t)bn * (Tc * 3);
    u64 xt2[Tc];
    #pragma unroll
    for (int t = 0; t < Tc; t++) { float v = xp[t * 3]; xt2[t] = pk2(v, v); }

    u64 ie2[16];
    #pragma unroll
    for (int hp = 0; hp < 16; hp++) {
        u64 acc = pk2(s_bi[2 * hp], s_bi[2 * hp + 1]);
        #pragma unroll
        for (int t = 0; t < Tc; t++) fma2(acc, xt2[t], s_wiT[t * 16 + hp]);
        ie2[hp] = acc;
    }
    // vectorized ie row store: [bn][32]
    #pragma unroll
    for (int hq = 0; hq < 8; hq++) {
        ulonglong2 v;
        v.x = ie2[2 * hq]; v.y = ie2[2 * hq + 1];
        *(ulonglong2*)&d_ie[(size_t)bn * Hc + hq * 4] = v;
    }

    // h0 row: [bn][64], hnode row [n][64]
    #pragma unroll 2
    for (int o4 = 0; o4 < 16; o4++) {
        float4 hn = *(const float4*)&d_hnode[(size_t)n * H2c + o4 * 4];
        float res[4];
        #pragma unroll
        for (int q = 0; q < 4; q++) {
            int o = o4 * 4 + q;
            u64 acc_a = 0ull, acc_b = 0ull;
            const ulonglong2* fl2 = (const ulonglong2*)&s_fl[o * Hc];
            #pragma unroll
            for (int k = 0; k < 8; k++) {
                ulonglong2 f = fl2[k];
                fma2(acc_a, ie2[2 * k + 0], f.x);
                fma2(acc_b, ie2[2 * k + 1], f.y);
            }
            float l0, h0v, l1, h1v;
            upk2(l0, h0v, acc_a);
            upk2(l1, h1v, acc_b);
            float base = (q == 0) ? hn.x : (q == 1) ? hn.y : (q == 2) ? hn.z : hn.w;
            res[q] = fmaxf(base + ((l0 + h0v) + (l1 + h1v)), 0.f);
        }
        *(float4*)&d_h0[(size_t)bn * H2c + o4 * 4] =
            make_float4(res[0], res[1], res[2], res[3]);
    }
}

// ---------------- Stage B: outer-product kv partials ----------------
__global__ void __launch_bounds__(256) kB()
{
    int b = blockIdx.y, p = blockIdx.x;
    int n0 = p * CHUNK;
    int n1 = min(n0 + CHUNK, Nc);
    int tid = threadIdx.x;
    int ty = tid >> 4;                  // 0..15: r-group (4 rows)
    int tx = tid & 15;                  // 0..15: c-group (4 cols)

    __shared__ float s_a[TJ][68];       // [k][r]  kp
    __shared__ float s_v[TJ][68];       // [k][c]  h0

    u64 acc2[4][2];
    #pragma unroll
    for (int i = 0; i < 4; i++) { acc2[i][0] = 0ull; acc2[i][1] = 0ull; }

    const float4 z4 = make_float4(0.f, 0.f, 0.f, 0.f);

    for (int jt = n0; jt < n1; jt += TJ) {
        int cnt = min(TJ, n1 - jt);
        // stage kp rows [n][r] — row-contiguous float4, coalesced
        for (int idx = tid; idx < TJ * 16; idx += 256) {
            int kk = idx >> 4, r4 = idx & 15;
            float4 v = (kk < cnt)
                ? *(const float4*)&d_kp[(size_t)(jt + kk) * Rc + r4 * 4] : z4;
            *(float4*)&s_a[kk][r4 * 4] = v;
        }
        // stage h0 rows [bn][c]
        for (int idx = tid; idx < TJ * 16; idx += 256) {
            int kk = idx >> 4, c4 = idx & 15;
            float4 v = (kk < cnt)
                ? *(const float4*)&d_h0[(size_t)(b * Nc + jt + kk) * H2c + c4 * 4] : z4;
            *(float4*)&s_v[kk][c4 * 4] = v;
        }
        __syncthreads();

        #pragma unroll 4
        for (int k = 0; k < TJ; k++) {
            float4 af = *(const float4*)&s_a[k][ty * 4];
            ulonglong2 bv = *(const ulonglong2*)&s_v[k][tx * 4];
            u64 a0 = pk2(af.x, af.x);
            u64 a1 = pk2(af.y, af.y);
            u64 a2 = pk2(af.z, af.z);
            u64 a3 = pk2(af.w, af.w);
            fma2(acc2[0][0], a0, bv.x); fma2(acc2[0][1], a0, bv.y);
            fma2(acc2[1][0], a1, bv.x); fma2(acc2[1][1], a1, bv.y);
            fma2(acc2[2][0], a2, bv.x); fma2(acc2[2][1], a2, bv.y);
            fma2(acc2[3][0], a3, bv.x); fma2(acc2[3][1], a3, bv.y);
        }
        __syncthreads();
    }

    #pragma unroll
    for (int i = 0; i < 4; i++) {
        float f0, f1, f2, f3;
        upk2(f0, f1, acc2[i][0]);
        upk2(f2, f3, acc2[i][1]);
        *(float4*)&d_kvpart[b][p][(ty * 4 + i) * H2c + tx * 4] =
            make_float4(f0, f1, f2, f3);
    }
}

// ---------------- reduce kv + den partials ----------------
__global__ void __launch_bounds__(256) kB2()
{
    int idx = blockIdx.x * 256 + threadIdx.x;
    if (idx < Bc * Rc * H2c) {
        int b = idx / (Rc * H2c), rc = idx % (Rc * H2c);
        float s = 0.f;
        for (int p = 0; p < PB; p++) s += d_kvpart[b][p][rc];
        d_kv[b][rc] = s;
    } else if (idx < Bc * Rc * H2c + Rc) {
        int r = idx - Bc * Rc * H2c;
        float s = 0.f;
        for (int k = 0; k < DEN_CHUNKS; k++) s += d_denpart[r][k];
        d_denv[r] = s;
    }
}

// ---------------- Stage C: vectorized rows; packed numerator + out GEMM ----------------
__global__ void __launch_bounds__(128) kC(
    const float* __restrict__ node_emb,
    const float* __restrict__ ln_g, const float* __restrict__ ln_b,
    const float* __restrict__ w_reg, const float* __restrict__ b_reg,
    float* __restrict__ out)
{
    int b = blockIdx.y;
    __shared__ u64  s_kv2[Rc * 32];            // kv as f32 pairs
    __shared__ u64  s_wr2[12 * 64];            // w_reg as f32 pairs
    __shared__ float s_den[Rc], s_g[H2c], s_be[H2c], s_br[12];
    int tid = threadIdx.x;
    {
        const ulonglong2* kvsrc = (const ulonglong2*)&d_kv[b][0];
        ulonglong2* kvdst = (ulonglong2*)s_kv2;
        for (int i = tid; i < Rc * 16; i += 128) kvdst[i] = kvsrc[i];
        const ulonglong2* wrsrc = (const ulonglong2*)w_reg;
        ulonglong2* wrdst = (ulonglong2*)s_wr2;
        for (int i = tid; i < 12 * 32; i += 128) wrdst[i] = wrsrc[i];
    }
    if (tid < Rc)  s_den[tid] = d_denv[tid];
    if (tid < H2c) { s_g[tid] = ln_g[tid]; s_be[tid] = ln_b[tid]; }
    if (tid < 12)  s_br[tid] = b_reg[tid];
    __syncthreads();

    int n = blockIdx.x * 128 + tid;
    if (n >= Nc) return;
    int bn = b * Nc + n;

    u64 h2[32];
    #pragma unroll
    for (int c = 0; c < 32; c++) h2[c] = 0ull;
    float den = 0.f;

    // qp row [n][r]: vectorized stream
    #pragma unroll 4
    for (int r4 = 0; r4 < 16; r4++) {
        float4 q4 = *(const float4*)&d_qp[(size_t)n * Rc + r4 * 4];
        #pragma unroll
        for (int q = 0; q < 4; q++) {
            int r = r4 * 4 + q;
            float qv = (q == 0) ? q4.x : (q == 1) ? q4.y : (q == 2) ? q4.z : q4.w;
            den += qv * s_den[r];
            u64 q2 = pk2(qv, qv);
            const ulonglong2* kvp = (const ulonglong2*)&s_kv2[r * 32];
            #pragma unroll
            for (int c8 = 0; c8 < 16; c8++) {
                ulonglong2 v = kvp[c8];
                fma2(h2[c8 * 2 + 0], q2, v.x);
                fma2(h2[c8 * 2 + 1], q2, v.y);
            }
        }
    }

    float h[H2c];
    #pragma unroll
    for (int c = 0; c < 32; c++) upk2(h[c * 2], h[c * 2 + 1], h2[c]);

    float inv = 1.f / den;
    u64 oacc[12];
    #pragma unroll
    for (int o = 0; o < 12; o++) oacc[o] = 0ull;

    float mu = 0.f;
    // ie part (c = 0..31): row [bn][32]
    #pragma unroll
    for (int c4 = 0; c4 < 8; c4++) {
        float4 va = *(const float4*)&d_ie[(size_t)bn * Hc + c4 * 4];
        h[c4 * 4 + 0] = h[c4 * 4 + 0] * inv + va.x; mu += h[c4 * 4 + 0];
        h[c4 * 4 + 1] = h[c4 * 4 + 1] * inv + va.y; mu += h[c4 * 4 + 1];
        h[c4 * 4 + 2] = h[c4 * 4 + 2] * inv + va.z; mu += h[c4 * 4 + 2];
        h[c4 * 4 + 3] = h[c4 * 4 + 3] * inv + va.w; mu += h[c4 * 4 + 3];
        u64 xp01 = pk2(fmaxf(va.x, 0.f), fmaxf(va.y, 0.f));
        u64 xp23 = pk2(fmaxf(va.z, 0.f), fmaxf(va.w, 0.f));
        #pragma unroll
        for (int o = 0; o < 12; o++) {
            ulonglong2 w = *(const ulonglong2*)&s_wr2[o * 64 + c4 * 2];
            fma2(oacc[o], xp01, w.x);
            fma2(oacc[o], xp23, w.y);
        }
    }
    // node part (c = 32..63): node_emb row [n][32]
    #pragma unroll
    for (int c4 = 8; c4 < 16; c4++) {
        float4 va = *(const float4*)&node_emb[(size_t)n * Hc + (c4 - 8) * 4];
        h[c4 * 4 + 0] = h[c4 * 4 + 0] * inv + va.x; mu += h[c4 * 4 + 0];
        h[c4 * 4 + 1] = h[c4 * 4 + 1] * inv + va.y; mu += h[c4 * 4 + 1];
        h[c4 * 4 + 2] = h[c4 * 4 + 2] * inv + va.z; mu += h[c4 * 4 + 2];
        h[c4 * 4 + 3] = h[c4 * 4 + 3] * inv + va.w; mu += h[c4 * 4 + 3];
        u64 xp01 = pk2(fmaxf(va.x, 0.f), fmaxf(va.y, 0.f));
        u64 xp23 = pk2(fmaxf(va.z, 0.f), fmaxf(va.w, 0.f));
        #pragma unroll
        for (int o = 0; o < 12; o++) {
            ulonglong2 w = *(const ulonglong2*)&s_wr2[o * 64 + c4 * 2];
            fma2(oacc[o], xp01, w.x);
            fma2(oacc[o], xp23, w.y);
        }
    }

    mu *= (1.f / H2c);
    float var = 0.f;
    #pragma unroll
    for (int c = 0; c < H2c; c++) { float d0 = h[c] - mu; var += d0 * d0; }
    var *= (1.f / H2c);
    float rstd = rsqrtf(var + EPS_LN);
    #pragma unroll
    for (int c = 0; c < H2c; c++)
        h[c] = fmaxf((h[c] - mu) * rstd * s_g[c] + s_be[c], 0.f);

    #pragma unroll
    for (int c4 = 0; c4 < 16; c4++) {
        u64 hp01 = pk2(h[c4 * 4 + 0], h[c4 * 4 + 1]);
        u64 hp23 = pk2(h[c4 * 4 + 2], h[c4 * 4 + 3]);
        #pragma unroll
        for (int o = 0; o < 12; o++) {
            ulonglong2 w = *(const ulonglong2*)&s_wr2[o * 64 + 32 + c4 * 2];
            fma2(oacc[o], hp01, w.x);
            fma2(oacc[o], hp23, w.y);
        }
    }

    float outr[12];
    #pragma unroll
    for (int o = 0; o < 12; o++) {
        float lo, hi;
        upk2(lo, hi, oacc[o]);
        outr[o] = s_br[o] + lo + hi;
    }
    float* op = out + (size_t)bn * 12;
    #pragma unroll
    for (int q = 0; q < 3; q++)
        *(float4*)&op[q * 4] = make_float4(outr[q * 4 + 0], outr[q * 4 + 1],
                                           outr[q * 4 + 2], outr[q * 4 + 3]);
}

// ---------------- launch ----------------
extern "C" void kernel_launch(void* const* d_in, const int* in_sizes, int n_in,
                              void* d_out, int out_size)
{
    (void)in_sizes; (void)n_in; (void)out_size;
    const float* x        = (const float*)d_in[0];
    const float* node_emb = (const float*)d_in[1];
    const float* w_input  = (const float*)d_in[4];
    const float* b_input  = (const float*)d_in[5];
    const float* w1       = (const float*)d_in[6];
    const float* b1       = (const float*)d_in[7];
    const float* w2       = (const float*)d_in[8];
    const float* b2       = (const float*)d_in[9];
    const float* fc_w     = (const float*)d_in[14];
    const float* fc_b     = (const float*)d_in[15];
    const float* ln_g     = (const float*)d_in[18];
    const float* ln_b     = (const float*)d_in[19];
    const float* w_reg    = (const float*)d_in[22];
    const float* b_reg    = (const float*)d_in[23];
    const float* rm1      = (const float*)d_in[24];
    float* out = (float*)d_out;

    kInit<<<1, 1>>>();
    kA<<<dim3(NBLK, 2), 128>>>(node_emb, w1, b1, w2, b2, rm1, fc_w, fc_b);
    kKP<<<DEN_CHUNKS, 256>>>();
    kV<<<(BNc + 127) / 128, 128>>>(x, w_input, b_input, fc_w);
    kB<<<dim3(PB, Bc), 256>>>();
    kB2<<<(Bc * Rc * H2c + Rc + 255) / 256, 256>>>();
    kC<<<dim3(NBLK, Bc), 128>>>(node_emb, ln_g, ln_b, w_reg, b_reg, out);
}

// round 11
// speedup vs baseline: 1.0412x; 1.0412x over previous
#include <cuda_runtime.h>
#include <math.h>

// ---------------- problem constants ----------------
#define Bc   4
#define Nc   50000
#define BNc  (Bc * Nc)
#define Tc   12
#define Hc   32
#define H2c  64
#define Rc   64

#define NRM     0.4204482076268573f   /* 32^-0.25 */
#define RATIO   0.125f                /* 64^-0.5  */
#define EPSP    1e-4f
#define EPS_LN  1e-5f

#define PB         391                /* kv partial blocks per batch */
#define CHUNK      128                /* nodes per kv block          */
#define TJ         32                 /* k tile in kv inner loop     */
#define NBLK       391                /* ceil(Nc/128)                */
#define DEN_CHUNKS 196                /* ceil(Nc/256)                */

typedef unsigned long long u64;

// ---------------- f32x2 packed math (Blackwell) ----------------
__device__ __forceinline__ u64 pk2(float a, float b) {
    u64 r;
    asm("mov.b64 %0, {%1, %2};" : "=l"(r) : "f"(a), "f"(b));
    return r;
}
__device__ __forceinline__ void fma2(u64& d, u64 a, u64 b) {
    asm("fma.rn.f32x2 %0, %1, %2, %0;" : "+l"(d) : "l"(a), "l"(b));
}
__device__ __forceinline__ void upk2(float& lo, float& hi, u64 v) {
    asm("mov.b64 {%0, %1}, %2;" : "=f"(lo), "=f"(hi) : "l"(v));
}

// ---------------- scratch (round-9 column-major layouts) ----------------
__device__ float    d_qp[Rc * Nc];
__device__ float    d_fk[Rc * Nc];
__device__ float    d_kp[Rc * Nc];
__device__ float    d_hnode[H2c * Nc];
__device__ float    d_neT[Hc * Nc];
__device__ float    d_h0[(size_t)H2c * BNc];
__device__ float    d_ie[(size_t)Hc * BNc];
__device__ unsigned d_keymax;
__device__ float    d_kv[Bc][Rc * H2c];
__device__ float    d_denv[Rc];
__device__ float    d_kvpart[Bc][PB][Rc * H2c];
__device__ float    d_denpart[Rc][DEN_CHUNKS];

__global__ void kInit() { d_keymax = 0u; }

__device__ __forceinline__ float decode_max(unsigned enc) {
    return (enc & 0x80000000u) ? __uint_as_float(enc ^ 0x80000000u)
                               : __uint_as_float(~enc);
}

// ---------------- Stage A: split y=0 queries (smem dd cache) | y=1 keys+hnode ----------------
__global__ void __launch_bounds__(128) kA(
    const float* __restrict__ node_emb,
    const float* __restrict__ w1, const float* __restrict__ b1,
    const float* __restrict__ w2, const float* __restrict__ b2,
    const float* __restrict__ rm1,
    const float* __restrict__ fc_w, const float* __restrict__ fc_b)
{
    __shared__ float sm[11424];
    int tid = threadIdx.x;
    int n = blockIdx.x * 128 + tid;

    if (blockIdx.y == 0) {
        // ---------- queries ----------
        float* s_w1 = sm;            // 1024
        float* s_rm = sm + 1024;     // 2048
        float* s_b1 = sm + 3072;     // 32
        float* s_dd = sm + 3104;     // 64*128 = 8192
        for (int i = tid; i < Hc * Hc; i += 128) s_w1[i] = w1[i];
        for (int i = tid; i < Rc * Hc; i += 128) s_rm[i] = rm1[i];
        if (tid < Hc) s_b1[tid] = b1[tid];
        __syncthreads();
        if (n >= Nc) return;

        float nd[Hc];
        #pragma unroll
        for (int d = 0; d < Hc; d++) nd[d] = node_emb[n * Hc + d];

        float nv[Hc];
        #pragma unroll
        for (int h = 0; h < Hc; h++) {
            float a = s_b1[h];
            #pragma unroll
            for (int d = 0; d < Hc; d++) a += nd[d] * s_w1[h * Hc + d];
            nv[h] = a;
        }
        float diag = 0.f;
        #pragma unroll
        for (int h = 0; h < Hc; h++) diag += nv[h] * nv[h];
        diag *= 0.5f * NRM * NRM;

        float mx = -3.0e38f;
        for (int r = 0; r < Rc; r++) {
            float a = 0.f;
            #pragma unroll
            for (int h = 0; h < Hc; h++) a += nv[h] * s_rm[r * Hc + h];
            a *= NRM;
            s_dd[r * 128 + tid] = a;
            mx = fmaxf(mx, a);
        }
        float base = diag + mx;
        for (int r = 0; r < Rc; r++)
            d_qp[r * Nc + n] = RATIO * (__expf(s_dd[r * 128 + tid] - base) + EPSP);
    } else {
        // ---------- keys + hnode + neT ----------
        float* s_w2 = sm;            // 1024
        float* s_rm = sm + 1024;     // 2048
        float* s_fr = sm + 3072;     // 2048
        float* s_b2 = sm + 5120;     // 32
        float* s_fb = sm + 5152;     // 64
        for (int i = tid; i < Hc * Hc; i += 128) s_w2[i] = w2[i];
        for (int i = tid; i < Rc * Hc; i += 128) s_rm[i] = rm1[i];
        for (int i = tid; i < H2c * Hc; i += 128) {
            int o = i / Hc, d = i % Hc;
            s_fr[i] = fc_w[o * H2c + Hc + d];
        }
        if (tid < Hc)  s_b2[tid] = b2[tid];
        if (tid < H2c) s_fb[tid] = fc_b[tid];
        __syncthreads();

        float kmaxdd = -3.0e38f;
        if (n < Nc) {
            float nd[Hc];
            #pragma unroll
            for (int d = 0; d < Hc; d++) nd[d] = node_emb[n * Hc + d];
            #pragma unroll
            for (int d = 0; d < Hc; d++) d_neT[d * Nc + n] = nd[d];

            float nv[Hc];
            #pragma unroll
            for (int h = 0; h < Hc; h++) {
                float a = s_b2[h];
                #pragma unroll
                for (int d = 0; d < Hc; d++) a += nd[d] * s_w2[h * Hc + d];
                nv[h] = a;
            }
            float diagk = 0.f;
            #pragma unroll
            for (int h = 0; h < Hc; h++) diagk += nv[h] * nv[h];
            diagk *= 0.5f * NRM * NRM;

            for (int r = 0; r < Rc; r++) {
                float a = 0.f;
                #pragma unroll
                for (int h = 0; h < Hc; h++) a += nv[h] * s_rm[r * Hc + h];
                a *= NRM;
                d_fk[r * Nc + n] = a - diagk;
                kmaxdd = fmaxf(kmaxdd, a);
            }

            for (int o = 0; o < H2c; o++) {
                float a = s_fb[o];
                #pragma unroll
                for (int d = 0; d < Hc; d++) a += nd[d] * s_fr[o * Hc + d];
                d_hnode[o * Nc + n] = a;
            }
        }
        #pragma unroll
        for (int off = 16; off; off >>= 1)
            kmaxdd = fmaxf(kmaxdd, __shfl_xor_sync(0xffffffffu, kmaxdd, off));
        if ((tid & 31) == 0) {
            unsigned bits = __float_as_uint(kmaxdd);
            unsigned enc = (bits & 0x80000000u) ? ~bits : (bits | 0x80000000u);
            atomicMax(&d_keymax, enc);
        }
    }
}

// ---------------- kKP: kp = ratio*(exp(fk - M) + eps) once; den partials ----------------
__global__ void __launch_bounds__(256) kKP()
{
    int r = blockIdx.y;
    int n = blockIdx.x * 256 + threadIdx.x;
    float M = decode_max(d_keymax);
    float v = 0.f;
    if (n < Nc) {
        v = RATIO * (__expf(d_fk[r * Nc + n] - M) + EPSP);
        d_kp[r * Nc + n] = v;
    }
    #pragma unroll
    for (int off = 16; off; off >>= 1)
        v += __shfl_xor_sync(0xffffffffu, v, off);
    __shared__ float red[8];
    if ((threadIdx.x & 31) == 0) red[threadIdx.x >> 5] = v;
    __syncthreads();
    if (threadIdx.x < 8) {
        float s = red[threadIdx.x];
        #pragma unroll
        for (int off = 4; off; off >>= 1)
            s += __shfl_xor_sync(0xffu, s, off);
        if (threadIdx.x == 0) d_denpart[r][blockIdx.x] = s;
    }
}

// ---------------- Stage V: smem-staged x + packed ie-GEMM + unrolled h0 GEMM ----------------
__global__ void __launch_bounds__(128, 7) kV(
    const float* __restrict__ x,
    const float* __restrict__ w_input, const float* __restrict__ b_input,
    const float* __restrict__ fc_w)
{
    __shared__ u64   s_wiT[Tc * 16];          // w_input transposed, f32x2 pairs [t][hp]
    __shared__ float s_bi[Hc], s_fl[H2c * Hc];
    __shared__ float s_x[128 * 13];           // only the t*3 elements, padded stride 13
    int tid = threadIdx.x;
    for (int i = tid; i < Tc * 16; i += 128) {
        int t = i >> 4, hp = i & 15;
        s_wiT[i] = pk2(w_input[(2 * hp) * Tc + t], w_input[(2 * hp + 1) * Tc + t]);
    }
    for (int i = tid; i < H2c * Hc; i += 128) {
        int o = i / Hc, d = i % Hc;
        s_fl[i] = fc_w[o * H2c + d];
    }
    if (tid < Hc) s_bi[tid] = b_input[tid];

    // coalesced float4 staging of x; keep only col%3==0 elements
    {
        size_t base = (size_t)blockIdx.x * (128 * 36);
        size_t total = (size_t)BNc * 36;
        int nv4 = (int)((total - base < (size_t)(128 * 36) ? total - base
                                                           : (size_t)(128 * 36)) >> 2);
        const float4* xp4 = (const float4*)(x + base);
        for (int i = tid; i < nv4; i += 128) {
            float4 v = xp4[i];
            int e = i * 4;
            int r0 = e / 36, c0 = e - r0 * 36;
            float vv[4] = {v.x, v.y, v.z, v.w};
            #pragma unroll
            for (int q = 0; q < 4; q++) {
                int r = r0, c = c0 + q;
                if (c >= 36) { r++; c -= 36; }
                if (c % 3 == 0) s_x[r * 13 + c / 3] = vv[q];
            }
        }
    }
    __syncthreads();

    int bn = blockIdx.x * 128 + tid;
    if (bn >= BNc) return;
    int n = bn % Nc;

    u64 xt2[Tc];
    #pragma unroll
    for (int t = 0; t < Tc; t++) { float v = s_x[tid * 13 + t]; xt2[t] = pk2(v, v); }

    u64 ie2[16];
    #pragma unroll
    for (int hp = 0; hp < 16; hp++) {
        u64 acc = pk2(s_bi[2 * hp], s_bi[2 * hp + 1]);
        #pragma unroll
        for (int t = 0; t < Tc; t++) fma2(acc, xt2[t], s_wiT[t * 16 + hp]);
        ie2[hp] = acc;
        float a0, a1;
        upk2(a0, a1, acc);
        d_ie[(size_t)(2 * hp) * BNc + bn] = a0;
        d_ie[(size_t)(2 * hp + 1) * BNc + bn] = a1;
    }

    #pragma unroll 4
    for (int o = 0; o < H2c; o++) {
        float hn = d_hnode[o * Nc + n];
        u64 acc_a = 0ull, acc_b = 0ull;
        const ulonglong2* fl2 = (const ulonglong2*)&s_fl[o * Hc];
        #pragma unroll
        for (int k = 0; k < 8; k++) {
            ulonglong2 f = fl2[k];
            fma2(acc_a, ie2[2 * k + 0], f.x);
            fma2(acc_b, ie2[2 * k + 1], f.y);
        }
        float l0, h0v, l1, h1v;
        upk2(l0, h0v, acc_a);
        upk2(l1, h1v, acc_b);
        float a = hn + ((l0 + h0v) + (l1 + h1v));
        d_h0[(size_t)o * BNc + bn] = fmaxf(a, 0.f);
    }
}

// ---------------- Stage B: 4r x 8c micro-tile kv partials ----------------
__global__ void __launch_bounds__(128) kB()
{
    int b = blockIdx.y, p = blockIdx.x;
    int n0 = p * CHUNK;
    int n1 = min(n0 + CHUNK, Nc);
    int tid = threadIdx.x;
    int ty = tid >> 3;                  // 0..15: r-group (4 rows)
    int tx = tid & 7;                   // 0..7 : c-group (8 cols)

    __shared__ float s_a[TJ][68];       // [k][r]  kp
    __shared__ float s_v[TJ][68];       // [k][c]  h0

    u64 acc2[4][4];
    #pragma unroll
    for (int i = 0; i < 4; i++)
        #pragma unroll
        for (int j = 0; j < 4; j++) acc2[i][j] = 0ull;

    for (int jt = n0; jt < n1; jt += TJ) {
        int cnt = min(TJ, n1 - jt);
        for (int idx = tid; idx < Rc * TJ; idx += 128) {
            int rr = idx >> 5, kk = idx & 31;
            s_a[kk][rr] = (kk < cnt) ? d_kp[rr * Nc + jt + kk] : 0.f;
        }
        for (int idx = tid; idx < H2c * TJ; idx += 128) {
            int cc = idx >> 5, kk = idx & 31;
            s_v[kk][cc] = (kk < cnt)
                ? d_h0[(size_t)cc * BNc + (size_t)b * Nc + jt + kk] : 0.f;
        }
        __syncthreads();

        #pragma unroll 4
        for (int k = 0; k < TJ; k++) {
            float4 af = *(const float4*)&s_a[k][ty * 4];
            ulonglong2 bv0 = *(const ulonglong2*)&s_v[k][tx * 8];
            ulonglong2 bv1 = *(const ulonglong2*)&s_v[k][tx * 8 + 4];
            u64 a0 = pk2(af.x, af.x);
            u64 a1 = pk2(af.y, af.y);
            u64 a2 = pk2(af.z, af.z);
            u64 a3 = pk2(af.w, af.w);
            fma2(acc2[0][0], a0, bv0.x); fma2(acc2[0][1], a0, bv0.y);
            fma2(acc2[0][2], a0, bv1.x); fma2(acc2[0][3], a0, bv1.y);
            fma2(acc2[1][0], a1, bv0.x); fma2(acc2[1][1], a1, bv0.y);
            fma2(acc2[1][2], a1, bv1.x); fma2(acc2[1][3], a1, bv1.y);
            fma2(acc2[2][0], a2, bv0.x); fma2(acc2[2][1], a2, bv0.y);
            fma2(acc2[2][2], a2, bv1.x); fma2(acc2[2][3], a2, bv1.y);
            fma2(acc2[3][0], a3, bv0.x); fma2(acc2[3][1], a3, bv0.y);
            fma2(acc2[3][2], a3, bv1.x); fma2(acc2[3][3], a3, bv1.y);
        }
        __syncthreads();
    }

    #pragma unroll
    for (int i = 0; i < 4; i++) {
        float f0, f1, f2, f3, f4, f5, f6, f7;
        upk2(f0, f1, acc2[i][0]);
        upk2(f2, f3, acc2[i][1]);
        upk2(f4, f5, acc2[i][2]);
        upk2(f6, f7, acc2[i][3]);
        float* dst = &d_kvpart[b][p][(ty * 4 + i) * H2c + tx * 8];
        *(float4*)&dst[0] = make_float4(f0, f1, f2, f3);
        *(float4*)&dst[4] = make_float4(f4, f5, f6, f7);
    }
}

// ---------------- reduce kv + den partials ----------------
__global__ void __launch_bounds__(256) kB2()
{
    int idx = blockIdx.x * 256 + threadIdx.x;
    if (idx < Bc * Rc * H2c) {
        int b = idx / (Rc * H2c), rc = idx % (Rc * H2c);
        float s = 0.f;
        for (int p = 0; p < PB; p++) s += d_kvpart[b][p][rc];
        d_kv[b][rc] = s;
    } else if (idx < Bc * Rc * H2c + Rc) {
        int r = idx - Bc * Rc * H2c;
        float s = 0.f;
        for (int k = 0; k < DEN_CHUNKS; k++) s += d_denpart[r][k];
        d_denv[r] = s;
    }
}

// ---------------- Stage C: packed-pair numerator + packed out GEMM (round-9) ----------------
__global__ void __launch_bounds__(128) kC(
    const float* __restrict__ ln_g, const float* __restrict__ ln_b,
    const float* __restrict__ w_reg, const float* __restrict__ b_reg,
    float* __restrict__ out)
{
    int b = blockIdx.y;
    __shared__ u64  s_kv2[Rc * 32];            // kv as f32 pairs
    __shared__ u64  s_wr2[12 * 64];            // w_reg as f32 pairs
    __shared__ float s_den[Rc], s_g[H2c], s_be[H2c], s_br[12];
    int tid = threadIdx.x;
    {
        const ulonglong2* kvsrc = (const ulonglong2*)&d_kv[b][0];
        ulonglong2* kvdst = (ulonglong2*)s_kv2;
        for (int i = tid; i < Rc * 16; i += 128) kvdst[i] = kvsrc[i];
        const ulonglong2* wrsrc = (const ulonglong2*)w_reg;
        ulonglong2* wrdst = (ulonglong2*)s_wr2;
        for (int i = tid; i < 12 * 32; i += 128) wrdst[i] = wrsrc[i];
    }
    if (tid < Rc)  s_den[tid] = d_denv[tid];
    if (tid < H2c) { s_g[tid] = ln_g[tid]; s_be[tid] = ln_b[tid]; }
    if (tid < 12)  s_br[tid] = b_reg[tid];
    __syncthreads();

    int n = blockIdx.x * 128 + tid;
    if (n >= Nc) return;
    int bn = b * Nc + n;

    u64 h2[32];
    #pragma unroll
    for (int c = 0; c < 32; c++) h2[c] = 0ull;
    float den = 0.f;

    #pragma unroll 4
    for (int r = 0; r < Rc; r++) {
        float q = d_qp[r * Nc + n];
        den += q * s_den[r];
        u64 q2 = pk2(q, q);
        const ulonglong2* kvp = (const ulonglong2*)&s_kv2[r * 32];
        #pragma unroll
        for (int c8 = 0; c8 < 16; c8++) {
            ulonglong2 v = kvp[c8];
            fma2(h2[c8 * 2 + 0], q2, v.x);
            fma2(h2[c8 * 2 + 1], q2, v.y);
        }
    }

    float h[H2c];
    #pragma unroll
    for (int c = 0; c < 32; c++) upk2(h[c * 2], h[c * 2 + 1], h2[c]);

    float inv = 1.f / den;
    u64 oacc[12];
    #pragma unroll
    for (int o = 0; o < 12; o++) oacc[o] = 0ull;

    float mu = 0.f;
    // ie part (c = 0..31)
    #pragma unroll
    for (int c4 = 0; c4 < 8; c4++) {
        float v0 = d_ie[(size_t)(c4 * 4 + 0) * BNc + bn];
        float v1 = d_ie[(size_t)(c4 * 4 + 1) * BNc + bn];
        float v2 = d_ie[(size_t)(c4 * 4 + 2) * BNc + bn];
        float v3 = d_ie[(size_t)(c4 * 4 + 3) * BNc + bn];
        h[c4 * 4 + 0] = h[c4 * 4 + 0] * inv + v0; mu += h[c4 * 4 + 0];
        h[c4 * 4 + 1] = h[c4 * 4 + 1] * inv + v1; mu += h[c4 * 4 + 1];
        h[c4 * 4 + 2] = h[c4 * 4 + 2] * inv + v2; mu += h[c4 * 4 + 2];
        h[c4 * 4 + 3] = h[c4 * 4 + 3] * inv + v3; mu += h[c4 * 4 + 3];
        u64 xp01 = pk2(fmaxf(v0, 0.f), fmaxf(v1, 0.f));
        u64 xp23 = pk2(fmaxf(v2, 0.f), fmaxf(v3, 0.f));
        #pragma unroll
        for (int o = 0; o < 12; o++) {
            ulonglong2 w = *(const ulonglong2*)&s_wr2[o * 64 + c4 * 2];
            fma2(oacc[o], xp01, w.x);
            fma2(oacc[o], xp23, w.y);
        }
    }
    // node part (c = 32..63)
    #pragma unroll
    for (int c4 = 8; c4 < 16; c4++) {
        float v0 = d_neT[(c4 * 4 + 0 - Hc) * Nc + n];
        float v1 = d_neT[(c4 * 4 + 1 - Hc) * Nc + n];
        float v2 = d_neT[(c4 * 4 + 2 - Hc) * Nc + n];
        float v3 = d_neT[(c4 * 4 + 3 - Hc) * Nc + n];
        h[c4 * 4 + 0] = h[c4 * 4 + 0] * inv + v0; mu += h[c4 * 4 + 0];
        h[c4 * 4 + 1] = h[c4 * 4 + 1] * inv + v1; mu += h[c4 * 4 + 1];
        h[c4 * 4 + 2] = h[c4 * 4 + 2] * inv + v2; mu += h[c4 * 4 + 2];
        h[c4 * 4 + 3] = h[c4 * 4 + 3] * inv + v3; mu += h[c4 * 4 + 3];
        u64 xp01 = pk2(fmaxf(v0, 0.f), fmaxf(v1, 0.f));
        u64 xp23 = pk2(fmaxf(v2, 0.f), fmaxf(v3, 0.f));
        #pragma unroll
        for (int o = 0; o < 12; o++) {
            ulonglong2 w = *(const ulonglong2*)&s_wr2[o * 64 + c4 * 2];
            fma2(oacc[o], xp01, w.x);
            fma2(oacc[o], xp23, w.y);
        }
    }

    mu *= (1.f / H2c);
    float var = 0.f;
    #pragma unroll
    for (int c = 0; c < H2c; c++) { float d0 = h[c] - mu; var += d0 * d0; }
    var *= (1.f / H2c);
    float rstd = rsqrtf(var + EPS_LN);
    #pragma unroll
    for (int c = 0; c < H2c; c++)
        h[c] = fmaxf((h[c] - mu) * rstd * s_g[c] + s_be[c], 0.f);

    #pragma unroll
    for (int c4 = 0; c4 < 16; c4++) {
        u64 hp01 = pk2(h[c4 * 4 + 0], h[c4 * 4 + 1]);
        u64 hp23 = pk2(h[c4 * 4 + 2], h[c4 * 4 + 3]);
        #pragma unroll
        for (int o = 0; o < 12; o++) {
            ulonglong2 w = *(const ulonglong2*)&s_wr2[o * 64 + 32 + c4 * 2];
            fma2(oacc[o], hp01, w.x);
            fma2(oacc[o], hp23, w.y);
        }
    }

    float* op = out + (size_t)bn * 12;
    #pragma unroll
    for (int o = 0; o < 12; o++) {
        float lo, hi;
        upk2(lo, hi, oacc[o]);
        op[o] = s_br[o] + lo + hi;
    }
}

// ---------------- launch ----------------
extern "C" void kernel_launch(void* const* d_in, const int* in_sizes, int n_in,
                              void* d_out, int out_size)
{
    (void)in_sizes; (void)n_in; (void)out_size;
    const float* x        = (const float*)d_in[0];
    const float* node_emb = (const float*)d_in[1];
    const float* w_input  = (const float*)d_in[4];
    const float* b_input  = (const float*)d_in[5];
    const float* w1       = (const float*)d_in[6];
    const float* b1       = (const float*)d_in[7];
    const float* w2       = (const float*)d_in[8];
    const float* b2       = (const float*)d_in[9];
    const float* fc_w     = (const float*)d_in[14];
    const float* fc_b     = (const float*)d_in[15];
    const float* ln_g     = (const float*)d_in[18];
    const float* ln_b     = (const float*)d_in[19];
    const float* w_reg    = (const float*)d_in[22];
    const float* b_reg    = (const float*)d_in[23];
    const float* rm1      = (const float*)d_in[24];
    float* out = (float*)d_out;

    kInit<<<1, 1>>>();
    kA<<<dim3(NBLK, 2), 128>>>(node_emb, w1, b1, w2, b2, rm1, fc_w, fc_b);
    kKP<<<dim3(DEN_CHUNKS, Rc), 256>>>();
    kV<<<(BNc + 127) / 128, 128>>>(x, w_input, b_input, fc_w);
    kB<<<dim3(PB, Bc), 128>>>();
    kB2<<<(Bc * Rc * H2c + Rc + 255) / 256, 256>>>();
    kC<<<dim3(NBLK, Bc), 128>>>(ln_g, ln_b, w_reg, b_reg, out);
}

// round 12
// speedup vs baseline: 1.2088x; 1.1610x over previous
#include <cuda_runtime.h>
#include <math.h>

// ---------------- problem constants ----------------
#define Bc   4
#define Nc   50000
#define BNc  (Bc * Nc)
#define Tc   12
#define Hc   32
#define H2c  64
#define Rc   64

#define NRM     0.4204482076268573f   /* 32^-0.25 */
#define RATIO   0.125f                /* 64^-0.5  */
#define EPSP    1e-4f
#define EPS_LN  1e-5f

#define PB         391                /* kv partial blocks per batch */
#define CHUNK      128                /* nodes per kv block          */
#define TJ         32                 /* k tile in kv inner loop     */
#define NBLK       391                /* ceil(Nc/128)                */
#define DEN_CHUNKS 196                /* ceil(Nc/256)                */

typedef unsigned long long u64;

// ---------------- f32x2 packed math (Blackwell) ----------------
__device__ __forceinline__ u64 pk2(float a, float b) {
    u64 r;
    asm("mov.b64 %0, {%1, %2};" : "=l"(r) : "f"(a), "f"(b));
    return r;
}
__device__ __forceinline__ void fma2(u64& d, u64 a, u64 b) {
    asm("fma.rn.f32x2 %0, %1, %2, %0;" : "+l"(d) : "l"(a), "l"(b));
}
__device__ __forceinline__ void upk2(float& lo, float& hi, u64 v) {
    asm("mov.b64 {%0, %1}, %2;" : "=f"(lo), "=f"(hi) : "l"(v));
}

// ---------------- scratch (round-9 column-major layouts) ----------------
__device__ float    d_qp[Rc * Nc];
__device__ float    d_fk[Rc * Nc];
__device__ float    d_kp[Rc * Nc];
__device__ float    d_hnode[H2c * Nc];
__device__ float    d_neT[Hc * Nc];
__device__ float    d_h0[(size_t)H2c * BNc];
__device__ float    d_ie[(size_t)Hc * BNc];
__device__ unsigned d_keymax;
__device__ float    d_kv[Bc][Rc * H2c];
__device__ float    d_denv[Rc];
__device__ float    d_kvpart[Bc][PB][Rc * H2c];
__device__ float    d_denpart[Rc][DEN_CHUNKS];

__global__ void kInit() { d_keymax = 0u; }

__device__ __forceinline__ float decode_max(unsigned enc) {
    return (enc & 0x80000000u) ? __uint_as_float(enc ^ 0x80000000u)
                               : __uint_as_float(~enc);
}

// ---------------- Stage A: f32x2-packed GEMMs. y=0 queries | y=1 keys+hnode ----------------
__global__ void __launch_bounds__(128) kA(
    const float* __restrict__ node_emb,
    const float* __restrict__ w1, const float* __restrict__ b1,
    const float* __restrict__ w2, const float* __restrict__ b2,
    const float* __restrict__ rm1,
    const float* __restrict__ fc_w, const float* __restrict__ fc_b)
{
    __shared__ __align__(16) char smraw[45440];
    u64* s_wP  = (u64*)smraw;                 // [d][hp] 512 u64
    u64* s_rmP = (u64*)(smraw + 4096);        // [h][rp] 1024 u64

    int tid = threadIdx.x;
    int n = blockIdx.x * 128 + tid;

    // rm packed pairs (both branches)
    for (int i = tid; i < 1024; i += 128) {
        int h = i >> 5, rp = i & 31;
        s_rmP[i] = pk2(rm1[(2 * rp) * Hc + h], rm1[(2 * rp + 1) * Hc + h]);
    }

    if (blockIdx.y == 0) {
        // ---------- queries ----------
        float* s_b1 = (float*)(smraw + 12288);   // 32 floats
        float* s_dd = (float*)(smraw + 12416);   // 64*128 floats
        for (int i = tid; i < 512; i += 128) {
            int d = i >> 4, hp = i & 15;
            s_wP[i] = pk2(w1[(2 * hp) * Hc + d], w1[(2 * hp + 1) * Hc + d]);
        }
        if (tid < Hc) s_b1[tid] = b1[tid];
        __syncthreads();
        if (n >= Nc) return;

        float nd[Hc];
        #pragma unroll
        for (int d = 0; d < Hc; d++) nd[d] = node_emb[n * Hc + d];

        u64 nvp[16];
        #pragma unroll
        for (int hp = 0; hp < 16; hp++) nvp[hp] = pk2(s_b1[2 * hp], s_b1[2 * hp + 1]);
        #pragma unroll
        for (int d = 0; d < Hc; d++) {
            u64 nd2 = pk2(nd[d], nd[d]);
            #pragma unroll
            for (int hp = 0; hp < 16; hp++) fma2(nvp[hp], nd2, s_wP[d * 16 + hp]);
        }

        u64 diag2 = 0ull;
        #pragma unroll
        for (int hp = 0; hp < 16; hp++) fma2(diag2, nvp[hp], nvp[hp]);
        float dl, dh;
        upk2(dl, dh, diag2);
        float diag = (dl + dh) * (0.5f * NRM * NRM);

        float nv[Hc];
        #pragma unroll
        for (int hp = 0; hp < 16; hp++) upk2(nv[2 * hp], nv[2 * hp + 1], nvp[hp]);

        float mx = -3.0e38f;
        for (int rpt = 0; rpt < 4; rpt++) {
            u64 ddp[8];
            #pragma unroll
            for (int j = 0; j < 8; j++) ddp[j] = 0ull;
            #pragma unroll
            for (int h = 0; h < Hc; h++) {
                u64 nv2 = pk2(nv[h], nv[h]);
                #pragma unroll
                for (int j = 0; j < 8; j++)
                    fma2(ddp[j], nv2, s_rmP[h * 32 + rpt * 8 + j]);
            }
            #pragma unroll
            for (int j = 0; j < 8; j++) {
                float a, bb;
                upk2(a, bb, ddp[j]);
                a *= NRM; bb *= NRM;
                s_dd[(rpt * 16 + 2 * j) * 128 + tid] = a;
                s_dd[(rpt * 16 + 2 * j + 1) * 128 + tid] = bb;
                mx = fmaxf(mx, fmaxf(a, bb));
            }
        }
        float base = diag + mx;
        for (int r = 0; r < Rc; r++)
            d_qp[r * Nc + n] = RATIO * (__expf(s_dd[r * 128 + tid] - base) + EPSP);
    } else {
        // ---------- keys + hnode + neT ----------
        u64*   s_frP = (u64*)(smraw + 12288);    // [d][op] 1024 u64
        float* s_b2  = (float*)(smraw + 20480);  // 32
        float* s_fb  = (float*)(smraw + 20608);  // 64
        for (int i = tid; i < 512; i += 128) {
            int d = i >> 4, hp = i & 15;
            s_wP[i] = pk2(w2[(2 * hp) * Hc + d], w2[(2 * hp + 1) * Hc + d]);
        }
        for (int i = tid; i < 1024; i += 128) {
            int d = i >> 5, op = i & 31;
            s_frP[i] = pk2(fc_w[(2 * op) * H2c + Hc + d],
                           fc_w[(2 * op + 1) * H2c + Hc + d]);
        }
        if (tid < Hc)  s_b2[tid] = b2[tid];
        if (tid < H2c) s_fb[tid] = fc_b[tid];
        __syncthreads();

        float kmaxdd = -3.0e38f;
        if (n < Nc) {
            float nd[Hc];
            #pragma unroll
            for (int d = 0; d < Hc; d++) nd[d] = node_emb[n * Hc + d];
            #pragma unroll
            for (int d = 0; d < Hc; d++) d_neT[d * Nc + n] = nd[d];

            u64 nvp[16];
            #pragma unroll
            for (int hp = 0; hp < 16; hp++) nvp[hp] = pk2(s_b2[2 * hp], s_b2[2 * hp + 1]);
            #pragma unroll
            for (int d = 0; d < Hc; d++) {
                u64 nd2 = pk2(nd[d], nd[d]);
                #pragma unroll
                for (int hp = 0; hp < 16; hp++) fma2(nvp[hp], nd2, s_wP[d * 16 + hp]);
            }

            u64 diag2 = 0ull;
            #pragma unroll
            for (int hp = 0; hp < 16; hp++) fma2(diag2, nvp[hp], nvp[hp]);
            float dl, dh;
            upk2(dl, dh, diag2);
            float diagk = (dl + dh) * (0.5f * NRM * NRM);

            float nv[Hc];
            #pragma unroll
            for (int hp = 0; hp < 16; hp++) upk2(nv[2 * hp], nv[2 * hp + 1], nvp[hp]);

            for (int rpt = 0; rpt < 4; rpt++) {
                u64 ddp[8];
                #pragma unroll
                for (int j = 0; j < 8; j++) ddp[j] = 0ull;
                #pragma unroll
                for (int h = 0; h < Hc; h++) {
                    u64 nv2 = pk2(nv[h], nv[h]);
                    #pragma unroll
                    for (int j = 0; j < 8; j++)
                        fma2(ddp[j], nv2, s_rmP[h * 32 + rpt * 8 + j]);
                }
                #pragma unroll
                for (int j = 0; j < 8; j++) {
                    float a, bb;
                    upk2(a, bb, ddp[j]);
                    a *= NRM; bb *= NRM;
                    d_fk[(rpt * 16 + 2 * j) * Nc + n] = a - diagk;
                    d_fk[(rpt * 16 + 2 * j + 1) * Nc + n] = bb - diagk;
                    kmaxdd = fmaxf(kmaxdd, fmaxf(a, bb));
                }
            }

            for (int opt = 0; opt < 4; opt++) {
                u64 hacc[8];
                #pragma unroll
                for (int j = 0; j < 8; j++) {
                    int op = opt * 8 + j;
                    hacc[j] = pk2(s_fb[2 * op], s_fb[2 * op + 1]);
                }
                #pragma unroll
                for (int d = 0; d < Hc; d++) {
                    u64 nd2 = pk2(nd[d], nd[d]);
                    #pragma unroll
                    for (int j = 0; j < 8; j++)
                        fma2(hacc[j], nd2, s_frP[d * 32 + opt * 8 + j]);
                }
                #pragma unroll
                for (int j = 0; j < 8; j++) {
                    float a, bb;
                    upk2(a, bb, hacc[j]);
                    d_hnode[(opt * 16 + 2 * j) * Nc + n] = a;
                    d_hnode[(opt * 16 + 2 * j + 1) * Nc + n] = bb;
                }
            }
        }
        #pragma unroll
        for (int off = 16; off; off >>= 1)
            kmaxdd = fmaxf(kmaxdd, __shfl_xor_sync(0xffffffffu, kmaxdd, off));
        if ((tid & 31) == 0) {
            unsigned bits = __float_as_uint(kmaxdd);
            unsigned enc = (bits & 0x80000000u) ? ~bits : (bits | 0x80000000u);
            atomicMax(&d_keymax, enc);
        }
    }
}

// ---------------- kKP: kp = ratio*(exp(fk - M) + eps) once; den partials ----------------
__global__ void __launch_bounds__(256) kKP()
{
    int r = blockIdx.y;
    int n = blockIdx.x * 256 + threadIdx.x;
    float M = decode_max(d_keymax);
    float v = 0.f;
    if (n < Nc) {
        v = RATIO * (__expf(d_fk[r * Nc + n] - M) + EPSP);
        d_kp[r * Nc + n] = v;
    }
    #pragma unroll
    for (int off = 16; off; off >>= 1)
        v += __shfl_xor_sync(0xffffffffu, v, off);
    __shared__ float red[8];
    if ((threadIdx.x & 31) == 0) red[threadIdx.x >> 5] = v;
    __syncthreads();
    if (threadIdx.x < 8) {
        float s = red[threadIdx.x];
        #pragma unroll
        for (int off = 4; off; off >>= 1)
            s += __shfl_xor_sync(0xffu, s, off);
        if (threadIdx.x == 0) d_denpart[r][blockIdx.x] = s;
    }
}

// ---------------- Stage V: packed ie-GEMM (t-outer, low regs) + unrolled h0 GEMM ----------------
__global__ void __launch_bounds__(128, 8) kV(
    const float* __restrict__ x,
    const float* __restrict__ w_input, const float* __restrict__ b_input,
    const float* __restrict__ fc_w)
{
    __shared__ u64   s_wiT[Tc * 16];          // w_input transposed, f32x2 pairs [t][hp]
    __shared__ float s_bi[Hc], s_fl[H2c * Hc];
    int tid = threadIdx.x;
    for (int i = tid; i < Tc * 16; i += 128) {
        int t = i >> 4, hp = i & 15;
        s_wiT[i] = pk2(w_input[(2 * hp) * Tc + t], w_input[(2 * hp + 1) * Tc + t]);
    }
    for (int i = tid; i < H2c * Hc; i += 128) {
        int o = i / Hc, d = i % Hc;
        s_fl[i] = fc_w[o * H2c + d];
    }
    if (tid < Hc) s_bi[tid] = b_input[tid];
    __syncthreads();

    int bn = blockIdx.x * 128 + tid;
    if (bn >= BNc) return;
    int n = bn % Nc;

    float xt[Tc];
    const float* xp = x + (size_t)bn * (Tc * 3);
    #pragma unroll
    for (int t = 0; t < Tc; t++) xt[t] = xp[t * 3];

    u64 ie2[16];
    #pragma unroll
    for (int hp = 0; hp < 16; hp++) ie2[hp] = pk2(s_bi[2 * hp], s_bi[2 * hp + 1]);
    #pragma unroll
    for (int t = 0; t < Tc; t++) {
        u64 xv = pk2(xt[t], xt[t]);
        #pragma unroll
        for (int hp = 0; hp < 16; hp++) fma2(ie2[hp], xv, s_wiT[t * 16 + hp]);
    }
    #pragma unroll
    for (int hp = 0; hp < 16; hp++) {
        float a0, a1;
        upk2(a0, a1, ie2[hp]);
        d_ie[(size_t)(2 * hp) * BNc + bn] = a0;
        d_ie[(size_t)(2 * hp + 1) * BNc + bn] = a1;
    }

    #pragma unroll 4
    for (int o = 0; o < H2c; o++) {
        float hn = d_hnode[o * Nc + n];
        u64 acc_a = 0ull, acc_b = 0ull;
        const ulonglong2* fl2 = (const ulonglong2*)&s_fl[o * Hc];
        #pragma unroll
        for (int k = 0; k < 8; k++) {
            ulonglong2 f = fl2[k];
            fma2(acc_a, ie2[2 * k + 0], f.x);
            fma2(acc_b, ie2[2 * k + 1], f.y);
        }
        float l0, h0v, l1, h1v;
        upk2(l0, h0v, acc_a);
        upk2(l1, h1v, acc_b);
        float a = hn + ((l0 + h0v) + (l1 + h1v));
        d_h0[(size_t)o * BNc + bn] = fmaxf(a, 0.f);
    }
}

// ---------------- Stage B: outer-product kv partials (round-9, 256 thr, 4r x 4c) ----------------
__global__ void __launch_bounds__(256) kB()
{
    int b = blockIdx.y, p = blockIdx.x;
    int n0 = p * CHUNK;
    int n1 = min(n0 + CHUNK, Nc);
    int tid = threadIdx.x;
    int ty = tid >> 4;                  // 0..15: r-group (4 rows)
    int tx = tid & 15;                  // 0..15: c-group (4 cols)

    __shared__ float s_a[TJ][68];       // [k][r]  kp
    __shared__ float s_v[TJ][68];       // [k][c]  h0

    u64 acc2[4][2];
    #pragma unroll
    for (int i = 0; i < 4; i++) { acc2[i][0] = 0ull; acc2[i][1] = 0ull; }

    for (int jt = n0; jt < n1; jt += TJ) {
        int cnt = min(TJ, n1 - jt);
        for (int idx = tid; idx < Rc * TJ; idx += 256) {
            int rr = idx >> 5, kk = idx & 31;
            s_a[kk][rr] = (kk < cnt) ? d_kp[rr * Nc + jt + kk] : 0.f;
        }
        for (int idx = tid; idx < H2c * TJ; idx += 256) {
            int cc = idx >> 5, kk = idx & 31;
            s_v[kk][cc] = (kk < cnt)
                ? d_h0[(size_t)cc * BNc + (size_t)b * Nc + jt + kk] : 0.f;
        }
        __syncthreads();

        #pragma unroll 4
        for (int k = 0; k < TJ; k++) {
            float4 af = *(const float4*)&s_a[k][ty * 4];
            ulonglong2 bv = *(const ulonglong2*)&s_v[k][tx * 4];
            u64 a0 = pk2(af.x, af.x);
            u64 a1 = pk2(af.y, af.y);
            u64 a2 = pk2(af.z, af.z);
            u64 a3 = pk2(af.w, af.w);
            fma2(acc2[0][0], a0, bv.x); fma2(acc2[0][1], a0, bv.y);
            fma2(acc2[1][0], a1, bv.x); fma2(acc2[1][1], a1, bv.y);
            fma2(acc2[2][0], a2, bv.x); fma2(acc2[2][1], a2, bv.y);
            fma2(acc2[3][0], a3, bv.x); fma2(acc2[3][1], a3, bv.y);
        }
        __syncthreads();
    }

    #pragma unroll
    for (int i = 0; i < 4; i++) {
        float f0, f1, f2, f3;
        upk2(f0, f1, acc2[i][0]);
        upk2(f2, f3, acc2[i][1]);
        *(float4*)&d_kvpart[b][p][(ty * 4 + i) * H2c + tx * 4] =
            make_float4(f0, f1, f2, f3);
    }
}

// ---------------- reduce kv + den partials ----------------
__global__ void __launch_bounds__(256) kB2()
{
    int idx = blockIdx.x * 256 + threadIdx.x;
    if (idx < Bc * Rc * H2c) {
        int b = idx / (Rc * H2c), rc = idx % (Rc * H2c);
        float s = 0.f;
        for (int p = 0; p < PB; p++) s += d_kvpart[b][p][rc];
        d_kv[b][rc] = s;
    } else if (idx < Bc * Rc * H2c + Rc) {
        int r = idx - Bc * Rc * H2c;
        float s = 0.f;
        for (int k = 0; k < DEN_CHUNKS; k++) s += d_denpart[r][k];
        d_denv[r] = s;
    }
}

// ---------------- Stage C: packed-pair numerator + packed out GEMM (round-9) ----------------
__global__ void __launch_bounds__(128) kC(
    const float* __restrict__ ln_g, const float* __restrict__ ln_b,
    const float* __restrict__ w_reg, const float* __restrict__ b_reg,
    float* __restrict__ out)
{
    int b = blockIdx.y;
    __shared__ u64  s_kv2[Rc * 32];            // kv as f32 pairs
    __shared__ u64  s_wr2[12 * 64];            // w_reg as f32 pairs
    __shared__ float s_den[Rc], s_g[H2c], s_be[H2c], s_br[12];
    int tid = threadIdx.x;
    {
        const ulonglong2* kvsrc = (const ulonglong2*)&d_kv[b][0];
        ulonglong2* kvdst = (ulonglong2*)s_kv2;
        for (int i = tid; i < Rc * 16; i += 128) kvdst[i] = kvsrc[i];
        const ulonglong2* wrsrc = (const ulonglong2*)w_reg;
        ulonglong2* wrdst = (ulonglong2*)s_wr2;
        for (int i = tid; i < 12 * 32; i += 128) wrdst[i] = wrsrc[i];
    }
    if (tid < Rc)  s_den[tid] = d_denv[tid];
    if (tid < H2c) { s_g[tid] = ln_g[tid]; s_be[tid] = ln_b[tid]; }
    if (tid < 12)  s_br[tid] = b_reg[tid];
    __syncthreads();

    int n = blockIdx.x * 128 + tid;
    if (n >= Nc) return;
    int bn = b * Nc + n;

    u64 h2[32];
    #pragma unroll
    for (int c = 0; c < 32; c++) h2[c] = 0ull;
    float den = 0.f;

    #pragma unroll 4
    for (int r = 0; r < Rc; r++) {
        float q = d_qp[r * Nc + n];
        den += q * s_den[r];
        u64 q2 = pk2(q, q);
        const ulonglong2* kvp = (const ulonglong2*)&s_kv2[r * 32];
        #pragma unroll
        for (int c8 = 0; c8 < 16; c8++) {
            ulonglong2 v = kvp[c8];
            fma2(h2[c8 * 2 + 0], q2, v.x);
            fma2(h2[c8 * 2 + 1], q2, v.y);
        }
    }

    float h[H2c];
    #pragma unroll
    for (int c = 0; c < 32; c++) upk2(h[c * 2], h[c * 2 + 1], h2[c]);

    float inv = 1.f / den;
    u64 oacc[12];
    #pragma unroll
    for (int o = 0; o < 12; o++) oacc[o] = 0ull;

    float mu = 0.f;
    // ie part (c = 0..31)
    #pragma unroll
    for (int c4 = 0; c4 < 8; c4++) {
        float v0 = d_ie[(size_t)(c4 * 4 + 0) * BNc + bn];
        float v1 = d_ie[(size_t)(c4 * 4 + 1) * BNc + bn];
        float v2 = d_ie[(size_t)(c4 * 4 + 2) * BNc + bn];
        float v3 = d_ie[(size_t)(c4 * 4 + 3) * BNc + bn];
        h[c4 * 4 + 0] = h[c4 * 4 + 0] * inv + v0; mu += h[c4 * 4 + 0];
        h[c4 * 4 + 1] = h[c4 * 4 + 1] * inv + v1; mu += h[c4 * 4 + 1];
        h[c4 * 4 + 2] = h[c4 * 4 + 2] * inv + v2; mu += h[c4 * 4 + 2];
        h[c4 * 4 + 3] = h[c4 * 4 + 3] * inv + v3; mu += h[c4 * 4 + 3];
        u64 xp01 = pk2(fmaxf(v0, 0.f), fmaxf(v1, 0.f));
        u64 xp23 = pk2(fmaxf(v2, 0.f), fmaxf(v3, 0.f));
        #pragma unroll
        for (int o = 0; o < 12; o++) {
            ulonglong2 w = *(const ulonglong2*)&s_wr2[o * 64 + c4 * 2];
            fma2(oacc[o], xp01, w.x);
            fma2(oacc[o], xp23, w.y);
        }
    }
    // node part (c = 32..63)
    #pragma unroll
    for (int c4 = 8; c4 < 16; c4++) {
        float v0 = d_neT[(c4 * 4 + 0 - Hc) * Nc + n];
        float v1 = d_neT[(c4 * 4 + 1 - Hc) * Nc + n];
        float v2 = d_neT[(c4 * 4 + 2 - Hc) * Nc + n];
        float v3 = d_neT[(c4 * 4 + 3 - Hc) * Nc + n];
        h[c4 * 4 + 0] = h[c4 * 4 + 0] * inv + v0; mu += h[c4 * 4 + 0];
        h[c4 * 4 + 1] = h[c4 * 4 + 1] * inv + v1; mu += h[c4 * 4 + 1];
        h[c4 * 4 + 2] = h[c4 * 4 + 2] * inv + v2; mu += h[c4 * 4 + 2];
        h[c4 * 4 + 3] = h[c4 * 4 + 3] * inv + v3; mu += h[c4 * 4 + 3];
        u64 xp01 = pk2(fmaxf(v0, 0.f), fmaxf(v1, 0.f));
        u64 xp23 = pk2(fmaxf(v2, 0.f), fmaxf(v3, 0.f));
        #pragma unroll
        for (int o = 0; o < 12; o++) {
            ulonglong2 w = *(const ulonglong2*)&s_wr2[o * 64 + c4 * 2];
            fma2(oacc[o], xp01, w.x);
            fma2(oacc[o], xp23, w.y);
        }
    }

    mu *= (1.f / H2c);
    float var = 0.f;
    #pragma unroll
    for (int c = 0; c < H2c; c++) { float d0 = h[c] - mu; var += d0 * d0; }
    var *= (1.f / H2c);
    float rstd = rsqrtf(var + EPS_LN);
    #pragma unroll
    for (int c = 0; c < H2c; c++)
        h[c] = fmaxf((h[c] - mu) * rstd * s_g[c] + s_be[c], 0.f);

    #pragma unroll
    for (int c4 = 0; c4 < 16; c4++) {
        u64 hp01 = pk2(h[c4 * 4 + 0], h[c4 * 4 + 1]);
        u64 hp23 = pk2(h[c4 * 4 + 2], h[c4 * 4 + 3]);
        #pragma unroll
        for (int o = 0; o < 12; o++) {
            ulonglong2 w = *(const ulonglong2*)&s_wr2[o * 64 + 32 + c4 * 2];
            fma2(oacc[o], hp01, w.x);
            fma2(oacc[o], hp23, w.y);
        }
    }

    float* op = out + (size_t)bn * 12;
    #pragma unroll
    for (int o = 0; o < 12; o++) {
        float lo, hi;
        upk2(lo, hi, oacc[o]);
        op[o] = s_br[o] + lo + hi;
    }
}

// ---------------- launch ----------------
extern "C" void kernel_launch(void* const* d_in, const int* in_sizes, int n_in,
                              void* d_out, int out_size)
{
    (void)in_sizes; (void)n_in; (void)out_size;
    const float* x        = (const float*)d_in[0];
    const float* node_emb = (const float*)d_in[1];
    const float* w_input  = (const float*)d_in[4];
    const float* b_input  = (const float*)d_in[5];
    const float* w1       = (const float*)d_in[6];
    const float* b1       = (const float*)d_in[7];
    const float* w2       = (const float*)d_in[8];
    const float* b2       = (const float*)d_in[9];
    const float* fc_w     = (const float*)d_in[14];
    const float* fc_b     = (const float*)d_in[15];
    const float* ln_g     = (const float*)d_in[18];
    const float* ln_b     = (const float*)d_in[19];
    const float* w_reg    = (const float*)d_in[22];
    const float* b_reg    = (const float*)d_in[23];
    const float* rm1      = (const float*)d_in[24];
    float* out = (float*)d_out;

    kInit<<<1, 1>>>();
    kA<<<dim3(NBLK, 2), 128>>>(node_emb, w1, b1, w2, b2, rm1, fc_w, fc_b);
    kKP<<<dim3(DEN_CHUNKS, Rc), 256>>>();
    kV<<<(BNc + 127) / 128, 128>>>(x, w_input, b_input, fc_w);
    kB<<<dim3(PB, Bc), 256>>>();
    kB2<<<(Bc * Rc * H2c + Rc + 255) / 256, 256>>>();
    kC<<<dim3(NBLK, Bc), 128>>>(ln_g, ln_b, w_reg, b_reg, out);
}

// round 13
// speedup vs baseline: 1.2407x; 1.0264x over previous
#include <cuda_runtime.h>
#include <math.h>

// ---------------- problem constants ----------------
#define Bc   4
#define Nc   50000
#define BNc  (Bc * Nc)
#define Tc   12
#define Hc   32
#define H2c  64
#define Rc   64

#define NRM     0.4204482076268573f   /* 32^-0.25 */
#define RATIO   0.125f                /* 64^-0.5  */
#define EPSP    1e-4f
#define EPS_LN  1e-5f

#define PB         391                /* kv partial blocks per batch */
#define CHUNK      128                /* nodes per kv block          */
#define TJ         32                 /* k tile in kv inner loop     */
#define NBLK       391                /* ceil(Nc/128)                */
#define DEN_CHUNKS 196                /* ceil(Nc/256)                */
#define KVB        782                /* ceil(BNc/256) kV-role blocks */

typedef unsigned long long u64;

// ---------------- f32x2 packed math (Blackwell) ----------------
__device__ __forceinline__ u64 pk2(float a, float b) {
    u64 r;
    asm("mov.b64 %0, {%1, %2};" : "=l"(r) : "f"(a), "f"(b));
    return r;
}
__device__ __forceinline__ void fma2(u64& d, u64 a, u64 b) {
    asm("fma.rn.f32x2 %0, %1, %2, %0;" : "+l"(d) : "l"(a), "l"(b));
}
__device__ __forceinline__ void upk2(float& lo, float& hi, u64 v) {
    asm("mov.b64 {%0, %1}, %2;" : "=f"(lo), "=f"(hi) : "l"(v));
}

// ---------------- scratch (column-major layouts) ----------------
__device__ float    d_qp[Rc * Nc];
__device__ float    d_fk[Rc * Nc];
__device__ float    d_kp[Rc * Nc];
__device__ float    d_hnode[H2c * Nc];
__device__ float    d_neT[Hc * Nc];
__device__ float    d_h0[(size_t)H2c * BNc];
__device__ float    d_ie[(size_t)Hc * BNc];
__device__ unsigned d_keymax;
__device__ float    d_kv[Bc][Rc * H2c];
__device__ float    d_denv[Rc];
__device__ float    d_kvpart[Bc][PB][Rc * H2c];
__device__ float    d_denpart[Rc][DEN_CHUNKS];

__global__ void kInit() { d_keymax = 0u; }

__device__ __forceinline__ float decode_max(unsigned enc) {
    return (enc & 0x80000000u) ? __uint_as_float(enc ^ 0x80000000u)
                               : __uint_as_float(~enc);
}

// ---------------- Stage A: f32x2-packed GEMMs. y=0 queries | y=1 keys+hnode ----------------
__global__ void __launch_bounds__(128) kA(
    const float* __restrict__ node_emb,
    const float* __restrict__ w1, const float* __restrict__ b1,
    const float* __restrict__ w2, const float* __restrict__ b2,
    const float* __restrict__ rm1,
    const float* __restrict__ fc_w, const float* __restrict__ fc_b)
{
    __shared__ __align__(16) char smraw[45440];
    u64* s_wP  = (u64*)smraw;                 // [d][hp] 512 u64
    u64* s_rmP = (u64*)(smraw + 4096);        // [h][rp] 1024 u64

    int tid = threadIdx.x;
    int n = blockIdx.x * 128 + tid;

    for (int i = tid; i < 1024; i += 128) {
        int h = i >> 5, rp = i & 31;
        s_rmP[i] = pk2(rm1[(2 * rp) * Hc + h], rm1[(2 * rp + 1) * Hc + h]);
    }

    if (blockIdx.y == 0) {
        // ---------- queries ----------
        float* s_b1 = (float*)(smraw + 12288);   // 32 floats
        float* s_dd = (float*)(smraw + 12416);   // 64*128 floats
        for (int i = tid; i < 512; i += 128) {
            int d = i >> 4, hp = i & 15;
            s_wP[i] = pk2(w1[(2 * hp) * Hc + d], w1[(2 * hp + 1) * Hc + d]);
        }
        if (tid < Hc) s_b1[tid] = b1[tid];
        __syncthreads();
        if (n >= Nc) return;

        float nd[Hc];
        #pragma unroll
        for (int d = 0; d < Hc; d++) nd[d] = node_emb[n * Hc + d];

        u64 nvp[16];
        #pragma unroll
        for (int hp = 0; hp < 16; hp++) nvp[hp] = pk2(s_b1[2 * hp], s_b1[2 * hp + 1]);
        #pragma unroll
        for (int d = 0; d < Hc; d++) {
            u64 nd2 = pk2(nd[d], nd[d]);
            #pragma unroll
            for (int hp = 0; hp < 16; hp++) fma2(nvp[hp], nd2, s_wP[d * 16 + hp]);
        }

        u64 diag2 = 0ull;
        #pragma unroll
        for (int hp = 0; hp < 16; hp++) fma2(diag2, nvp[hp], nvp[hp]);
        float dl, dh;
        upk2(dl, dh, diag2);
        float diag = (dl + dh) * (0.5f * NRM * NRM);

        float nv[Hc];
        #pragma unroll
        for (int hp = 0; hp < 16; hp++) upk2(nv[2 * hp], nv[2 * hp + 1], nvp[hp]);

        float mx = -3.0e38f;
        for (int rpt = 0; rpt < 4; rpt++) {
            u64 ddp[8];
            #pragma unroll
            for (int j = 0; j < 8; j++) ddp[j] = 0ull;
            #pragma unroll
            for (int h = 0; h < Hc; h++) {
                u64 nv2 = pk2(nv[h], nv[h]);
                #pragma unroll
                for (int j = 0; j < 8; j++)
                    fma2(ddp[j], nv2, s_rmP[h * 32 + rpt * 8 + j]);
            }
            #pragma unroll
            for (int j = 0; j < 8; j++) {
                float a, bb;
                upk2(a, bb, ddp[j]);
                a *= NRM; bb *= NRM;
                s_dd[(rpt * 16 + 2 * j) * 128 + tid] = a;
                s_dd[(rpt * 16 + 2 * j + 1) * 128 + tid] = bb;
                mx = fmaxf(mx, fmaxf(a, bb));
            }
        }
        float base = diag + mx;
        for (int r = 0; r < Rc; r++)
            d_qp[r * Nc + n] = RATIO * (__expf(s_dd[r * 128 + tid] - base) + EPSP);
    } else {
        // ---------- keys + hnode + neT ----------
        u64*   s_frP = (u64*)(smraw + 12288);    // [d][op] 1024 u64
        float* s_b2  = (float*)(smraw + 20480);  // 32
        float* s_fb  = (float*)(smraw + 20608);  // 64
        for (int i = tid; i < 512; i += 128) {
            int d = i >> 4, hp = i & 15;
            s_wP[i] = pk2(w2[(2 * hp) * Hc + d], w2[(2 * hp + 1) * Hc + d]);
        }
        for (int i = tid; i < 1024; i += 128) {
            int d = i >> 5, op = i & 31;
            s_frP[i] = pk2(fc_w[(2 * op) * H2c + Hc + d],
                           fc_w[(2 * op + 1) * H2c + Hc + d]);
        }
        if (tid < Hc)  s_b2[tid] = b2[tid];
        if (tid < H2c) s_fb[tid] = fc_b[tid];
        __syncthreads();

        float kmaxdd = -3.0e38f;
        if (n < Nc) {
            float nd[Hc];
            #pragma unroll
            for (int d = 0; d < Hc; d++) nd[d] = node_emb[n * Hc + d];
            #pragma unroll
            for (int d = 0; d < Hc; d++) d_neT[d * Nc + n] = nd[d];

            u64 nvp[16];
            #pragma unroll
            for (int hp = 0; hp < 16; hp++) nvp[hp] = pk2(s_b2[2 * hp], s_b2[2 * hp + 1]);
            #pragma unroll
            for (int d = 0; d < Hc; d++) {
                u64 nd2 = pk2(nd[d], nd[d]);
                #pragma unroll
                for (int hp = 0; hp < 16; hp++) fma2(nvp[hp], nd2, s_wP[d * 16 + hp]);
            }

            u64 diag2 = 0ull;
            #pragma unroll
            for (int hp = 0; hp < 16; hp++) fma2(diag2, nvp[hp], nvp[hp]);
            float dl, dh;
            upk2(dl, dh, diag2);
            float diagk = (dl + dh) * (0.5f * NRM * NRM);

            float nv[Hc];
            #pragma unroll
            for (int hp = 0; hp < 16; hp++) upk2(nv[2 * hp], nv[2 * hp + 1], nvp[hp]);

            for (int rpt = 0; rpt < 4; rpt++) {
                u64 ddp[8];
                #pragma unroll
                for (int j = 0; j < 8; j++) ddp[j] = 0ull;
                #pragma unroll
                for (int h = 0; h < Hc; h++) {
                    u64 nv2 = pk2(nv[h], nv[h]);
                    #pragma unroll
                    for (int j = 0; j < 8; j++)
                        fma2(ddp[j], nv2, s_rmP[h * 32 + rpt * 8 + j]);
                }
                #pragma unroll
                for (int j = 0; j < 8; j++) {
                    float a, bb;
                    upk2(a, bb, ddp[j]);
                    a *= NRM; bb *= NRM;
                    d_fk[(rpt * 16 + 2 * j) * Nc + n] = a - diagk;
                    d_fk[(rpt * 16 + 2 * j + 1) * Nc + n] = bb - diagk;
                    kmaxdd = fmaxf(kmaxdd, fmaxf(a, bb));
                }
            }

            for (int opt = 0; opt < 4; opt++) {
                u64 hacc[8];
                #pragma unroll
                for (int j = 0; j < 8; j++) {
                    int op = opt * 8 + j;
                    hacc[j] = pk2(s_fb[2 * op], s_fb[2 * op + 1]);
                }
                #pragma unroll
                for (int d = 0; d < Hc; d++) {
                    u64 nd2 = pk2(nd[d], nd[d]);
                    #pragma unroll
                    for (int j = 0; j < 8; j++)
                        fma2(hacc[j], nd2, s_frP[d * 32 + opt * 8 + j]);
                }
                #pragma unroll
                for (int j = 0; j < 8; j++) {
                    float a, bb;
                    upk2(a, bb, hacc[j]);
                    d_hnode[(opt * 16 + 2 * j) * Nc + n] = a;
                    d_hnode[(opt * 16 + 2 * j + 1) * Nc + n] = bb;
                }
            }
        }
        #pragma unroll
        for (int off = 16; off; off >>= 1)
            kmaxdd = fmaxf(kmaxdd, __shfl_xor_sync(0xffffffffu, kmaxdd, off));
        if ((tid & 31) == 0) {
            unsigned bits = __float_as_uint(kmaxdd);
            unsigned enc = (bits & 0x80000000u) ? ~bits : (bits | 0x80000000u);
            atomicMax(&d_keymax, enc);
        }
    }
}

// ---------------- fused kV + kKP: blocks [0,KVB) do ie/h0; rest do kp/den ----------------
__global__ void __launch_bounds__(256, 4) kVP(
    const float* __restrict__ x,
    const float* __restrict__ w_input, const float* __restrict__ b_input,
    const float* __restrict__ fc_w)
{
    __shared__ u64   s_wiT[Tc * 16];
    __shared__ float s_bi[Hc], s_fl[H2c * Hc];
    __shared__ float s_red[8];
    int tid = threadIdx.x;

    if (blockIdx.x < KVB) {
        // ---------------- kV role ----------------
        for (int i = tid; i < Tc * 16; i += 256) {
            int t = i >> 4, hp = i & 15;
            s_wiT[i] = pk2(w_input[(2 * hp) * Tc + t], w_input[(2 * hp + 1) * Tc + t]);
        }
        for (int i = tid; i < H2c * Hc; i += 256) {
            int o = i / Hc, d = i % Hc;
            s_fl[i] = fc_w[o * H2c + d];
        }
        if (tid < Hc) s_bi[tid] = b_input[tid];
        __syncthreads();

        int bn = blockIdx.x * 256 + tid;
        if (bn >= BNc) return;
        int n = bn % Nc;

        float xt[Tc];
        const float* xp = x + (size_t)bn * (Tc * 3);
        #pragma unroll
        for (int t = 0; t < Tc; t++) xt[t] = xp[t * 3];

        u64 ie2[16];
        #pragma unroll
        for (int hp = 0; hp < 16; hp++) ie2[hp] = pk2(s_bi[2 * hp], s_bi[2 * hp + 1]);
        #pragma unroll
        for (int t = 0; t < Tc; t++) {
            u64 xv = pk2(xt[t], xt[t]);
            #pragma unroll
            for (int hp = 0; hp < 16; hp++) fma2(ie2[hp], xv, s_wiT[t * 16 + hp]);
        }
        #pragma unroll
        for (int hp = 0; hp < 16; hp++) {
            float a0, a1;
            upk2(a0, a1, ie2[hp]);
            d_ie[(size_t)(2 * hp) * BNc + bn] = a0;
            d_ie[(size_t)(2 * hp + 1) * BNc + bn] = a1;
        }

        #pragma unroll 4
        for (int o = 0; o < H2c; o++) {
            float hn = d_hnode[o * Nc + n];
            u64 acc_a = 0ull, acc_b = 0ull;
            const ulonglong2* fl2 = (const ulonglong2*)&s_fl[o * Hc];
            #pragma unroll
            for (int k = 0; k < 8; k++) {
                ulonglong2 f = fl2[k];
                fma2(acc_a, ie2[2 * k + 0], f.x);
                fma2(acc_b, ie2[2 * k + 1], f.y);
            }
            float l0, h0v, l1, h1v;
            upk2(l0, h0v, acc_a);
            upk2(l1, h1v, acc_b);
            float a = hn + ((l0 + h0v) + (l1 + h1v));
            d_h0[(size_t)o * BNc + bn] = fmaxf(a, 0.f);
        }
    } else {
        // ---------------- kKP role ----------------
        int idx = blockIdx.x - KVB;           // 0 .. Rc*DEN_CHUNKS-1
        int r = idx / DEN_CHUNKS;
        int chunk = idx - r * DEN_CHUNKS;
        int n = chunk * 256 + tid;
        float M = decode_max(d_keymax);
        float v = 0.f;
        if (n < Nc) {
            v = RATIO * (__expf(d_fk[r * Nc + n] - M) + EPSP);
            d_kp[r * Nc + n] = v;
        }
        #pragma unroll
        for (int off = 16; off; off >>= 1)
            v += __shfl_xor_sync(0xffffffffu, v, off);
        if ((tid & 31) == 0) s_red[tid >> 5] = v;
        __syncthreads();
        if (tid < 8) {
            float s = s_red[tid];
            #pragma unroll
            for (int off = 4; off; off >>= 1)
                s += __shfl_xor_sync(0xffu, s, off);
            if (tid == 0) d_denpart[r][chunk] = s;
        }
    }
}

// ---------------- Stage B: 2-batch merged kv partials ----------------
__global__ void __launch_bounds__(256) kB()
{
    int bb = blockIdx.y * 2;            // base batch (0 or 2)
    int p = blockIdx.x;
    int n0 = p * CHUNK;
    int n1 = min(n0 + CHUNK, Nc);
    int tid = threadIdx.x;
    int ty = tid >> 4;                  // 0..15: r-group (4 rows)
    int tx = tid & 15;                  // 0..15: c-group (4 cols)

    __shared__ float s_a[TJ][68];       // [k][r]  kp
    __shared__ float s_v[2][TJ][68];    // [b2][k][c]  h0

    u64 acc2[2][4][2];
    #pragma unroll
    for (int b2 = 0; b2 < 2; b2++)
        #pragma unroll
        for (int i = 0; i < 4; i++) { acc2[b2][i][0] = 0ull; acc2[b2][i][1] = 0ull; }

    for (int jt = n0; jt < n1; jt += TJ) {
        int cnt = min(TJ, n1 - jt);
        for (int idx = tid; idx < Rc * TJ; idx += 256) {
            int rr = idx >> 5, kk = idx & 31;
            s_a[kk][rr] = (kk < cnt) ? d_kp[rr * Nc + jt + kk] : 0.f;
        }
        for (int idx = tid; idx < 2 * H2c * TJ; idx += 256) {
            int b2 = idx >> 11;
            int rem = idx & 2047;
            int cc = rem >> 5, kk = rem & 31;
            s_v[b2][kk][cc] = (kk < cnt)
                ? d_h0[(size_t)cc * BNc + (size_t)(bb + b2) * Nc + jt + kk] : 0.f;
        }
        __syncthreads();

        #pragma unroll 2
        for (int k = 0; k < TJ; k++) {
            float4 af = *(const float4*)&s_a[k][ty * 4];
            u64 a0 = pk2(af.x, af.x);
            u64 a1 = pk2(af.y, af.y);
            u64 a2 = pk2(af.z, af.z);
            u64 a3 = pk2(af.w, af.w);
            #pragma unroll
            for (int b2 = 0; b2 < 2; b2++) {
                ulonglong2 bv = *(const ulonglong2*)&s_v[b2][k][tx * 4];
                fma2(acc2[b2][0][0], a0, bv.x); fma2(acc2[b2][0][1], a0, bv.y);
                fma2(acc2[b2][1][0], a1, bv.x); fma2(acc2[b2][1][1], a1, bv.y);
                fma2(acc2[b2][2][0], a2, bv.x); fma2(acc2[b2][2][1], a2, bv.y);
                fma2(acc2[b2][3][0], a3, bv.x); fma2(acc2[b2][3][1], a3, bv.y);
            }
        }
        __syncthreads();
    }

    #pragma unroll
    for (int b2 = 0; b2 < 2; b2++)
        #pragma unroll
        for (int i = 0; i < 4; i++) {
            float f0, f1, f2, f3;
            upk2(f0, f1, acc2[b2][i][0]);
            upk2(f2, f3, acc2[b2][i][1]);
            *(float4*)&d_kvpart[bb + b2][p][(ty * 4 + i) * H2c + tx * 4] =
                make_float4(f0, f1, f2, f3);
        }
}

// ---------------- reduce kv + den partials ----------------
__global__ void __launch_bounds__(256) kB2()
{
    int idx = blockIdx.x * 256 + threadIdx.x;
    if (idx < Bc * Rc * H2c) {
        int b = idx / (Rc * H2c), rc = idx % (Rc * H2c);
        float s = 0.f;
        for (int p = 0; p < PB; p++) s += d_kvpart[b][p][rc];
        d_kv[b][rc] = s;
    } else if (idx < Bc * Rc * H2c + Rc) {
        int r = idx - Bc * Rc * H2c;
        float s = 0.f;
        for (int k = 0; k < DEN_CHUNKS; k++) s += d_denpart[r][k];
        d_denv[r] = s;
    }
}

// ---------------- Stage C: packed-pair numerator + packed out GEMM ----------------
__global__ void __launch_bounds__(128) kC(
    const float* __restrict__ ln_g, const float* __restrict__ ln_b,
    const float* __restrict__ w_reg, const float* __restrict__ b_reg,
    float* __restrict__ out)
{
    int b = blockIdx.y;
    __shared__ u64  s_kv2[Rc * 32];            // kv as f32 pairs
    __shared__ u64  s_wr2[12 * 64];            // w_reg as f32 pairs
    __shared__ float s_den[Rc], s_g[H2c], s_be[H2c], s_br[12];
    int tid = threadIdx.x;
    {
        const ulonglong2* kvsrc = (const ulonglong2*)&d_kv[b][0];
        ulonglong2* kvdst = (ulonglong2*)s_kv2;
        for (int i = tid; i < Rc * 16; i += 128) kvdst[i] = kvsrc[i];
        const ulonglong2* wrsrc = (const ulonglong2*)w_reg;
        ulonglong2* wrdst = (ulonglong2*)s_wr2;
        for (int i = tid; i < 12 * 32; i += 128) wrdst[i] = wrsrc[i];
    }
    if (tid < Rc)  s_den[tid] = d_denv[tid];
    if (tid < H2c) { s_g[tid] = ln_g[tid]; s_be[tid] = ln_b[tid]; }
    if (tid < 12)  s_br[tid] = b_reg[tid];
    __syncthreads();

    int n = blockIdx.x * 128 + tid;
    if (n >= Nc) return;
    int bn = b * Nc + n;

    u64 h2[32];
    #pragma unroll
    for (int c = 0; c < 32; c++) h2[c] = 0ull;
    float den = 0.f;

    #pragma unroll 4
    for (int r = 0; r < Rc; r++) {
        float q = d_qp[r * Nc + n];
        den += q * s_den[r];
        u64 q2 = pk2(q, q);
        const ulonglong2* kvp = (const ulonglong2*)&s_kv2[r * 32];
        #pragma unroll
        for (int c8 = 0; c8 < 16; c8++) {
            ulonglong2 v = kvp[c8];
            fma2(h2[c8 * 2 + 0], q2, v.x);
            fma2(h2[c8 * 2 + 1], q2, v.y);
        }
    }

    float h[H2c];
    #pragma unroll
    for (int c = 0; c < 32; c++) upk2(h[c * 2], h[c * 2 + 1], h2[c]);

    float inv = 1.f / den;
    u64 oacc[12];
    #pragma unroll
    for (int o = 0; o < 12; o++) oacc[o] = 0ull;

    float mu = 0.f;
    // ie part (c = 0..31)
    #pragma unroll
    for (int c4 = 0; c4 < 8; c4++) {
        float v0 = d_ie[(size_t)(c4 * 4 + 0) * BNc + bn];
        float v1 = d_ie[(size_t)(c4 * 4 + 1) * BNc + bn];
        float v2 = d_ie[(size_t)(c4 * 4 + 2) * BNc + bn];
        float v3 = d_ie[(size_t)(c4 * 4 + 3) * BNc + bn];
        h[c4 * 4 + 0] = h[c4 * 4 + 0] * inv + v0; mu += h[c4 * 4 + 0];
        h[c4 * 4 + 1] = h[c4 * 4 + 1] * inv + v1; mu += h[c4 * 4 + 1];
        h[c4 * 4 + 2] = h[c4 * 4 + 2] * inv + v2; mu += h[c4 * 4 + 2];
        h[c4 * 4 + 3] = h[c4 * 4 + 3] * inv + v3; mu += h[c4 * 4 + 3];
        u64 xp01 = pk2(fmaxf(v0, 0.f), fmaxf(v1, 0.f));
        u64 xp23 = pk2(fmaxf(v2, 0.f), fmaxf(v3, 0.f));
        #pragma unroll
        for (int o = 0; o < 12; o++) {
            ulonglong2 w = *(const ulonglong2*)&s_wr2[o * 64 + c4 * 2];
            fma2(oacc[o], xp01, w.x);
            fma2(oacc[o], xp23, w.y);
        }
    }
    // node part (c = 32..63)
    #pragma unroll
    for (int c4 = 8; c4 < 16; c4++) {
        float v0 = d_neT[(c4 * 4 + 0 - Hc) * Nc + n];
        float v1 = d_neT[(c4 * 4 + 1 - Hc) * Nc + n];
        float v2 = d_neT[(c4 * 4 + 2 - Hc) * Nc + n];
        float v3 = d_neT[(c4 * 4 + 3 - Hc) * Nc + n];
        h[c4 * 4 + 0] = h[c4 * 4 + 0] * inv + v0; mu += h[c4 * 4 + 0];
        h[c4 * 4 + 1] = h[c4 * 4 + 1] * inv + v1; mu += h[c4 * 4 + 1];
        h[c4 * 4 + 2] = h[c4 * 4 + 2] * inv + v2; mu += h[c4 * 4 + 2];
        h[c4 * 4 + 3] = h[c4 * 4 + 3] * inv + v3; mu += h[c4 * 4 + 3];
        u64 xp01 = pk2(fmaxf(v0, 0.f), fmaxf(v1, 0.f));
        u64 xp23 = pk2(fmaxf(v2, 0.f), fmaxf(v3, 0.f));
        #pragma unroll
        for (int o = 0; o < 12; o++) {
            ulonglong2 w = *(const ulonglong2*)&s_wr2[o * 64 + c4 * 2];
            fma2(oacc[o], xp01, w.x);
            fma2(oacc[o], xp23, w.y);
        }
    }

    mu *= (1.f / H2c);
    float var = 0.f;
    #pragma unroll
    for (int c = 0; c < H2c; c++) { float d0 = h[c] - mu; var += d0 * d0; }
    var *= (1.f / H2c);
    float rstd = rsqrtf(var + EPS_LN);
    #pragma unroll
    for (int c = 0; c < H2c; c++)
        h[c] = fmaxf((h[c] - mu) * rstd * s_g[c] + s_be[c], 0.f);

    #pragma unroll
    for (int c4 = 0; c4 < 16; c4++) {
        u64 hp01 = pk2(h[c4 * 4 + 0], h[c4 * 4 + 1]);
        u64 hp23 = pk2(h[c4 * 4 + 2], h[c4 * 4 + 3]);
        #pragma unroll
        for (int o = 0; o < 12; o++) {
            ulonglong2 w = *(const ulonglong2*)&s_wr2[o * 64 + 32 + c4 * 2];
            fma2(oacc[o], hp01, w.x);
            fma2(oacc[o], hp23, w.y);
        }
    }

    float* op = out + (size_t)bn * 12;
    #pragma unroll
    for (int o = 0; o < 12; o++) {
        float lo, hi;
        upk2(lo, hi, oacc[o]);
        op[o] = s_br[o] + lo + hi;
    }
}

// ---------------- launch ----------------
extern "C" void kernel_launch(void* const* d_in, const int* in_sizes, int n_in,
                              void* d_out, int out_size)
{
    (void)in_sizes; (void)n_in; (void)out_size;
    const float* x        = (const float*)d_in[0];
    const float* node_emb = (const float*)d_in[1];
    const float* w_input  = (const float*)d_in[4];
    const float* b_input  = (const float*)d_in[5];
    const float* w1       = (const float*)d_in[6];
    const float* b1       = (const float*)d_in[7];
    const float* w2       = (const float*)d_in[8];
    const float* b2       = (const float*)d_in[9];
    const float* fc_w     = (const float*)d_in[14];
    const float* fc_b     = (const float*)d_in[15];
    const float* ln_g     = (const float*)d_in[18];
    const float* ln_b     = (const float*)d_in[19];
    const float* w_reg    = (const float*)d_in[22];
    const float* b_reg    = (const float*)d_in[23];
    const float* rm1      = (const float*)d_in[24];
    float* out = (float*)d_out;

    kInit<<<1, 1>>>();
    kA<<<dim3(NBLK, 2), 128>>>(node_emb, w1, b1, w2, b2, rm1, fc_w, fc_b);
    kVP<<<KVB + Rc * DEN_CHUNKS, 256>>>(x, w_input, b_input, fc_w);
    kB<<<dim3(PB, 2), 256>>>();
    kB2<<<(Bc * Rc * H2c + Rc + 255) / 256, 256>>>();
    kC<<<dim3(NBLK, Bc), 128>>>(ln_g, ln_b, w_reg, b_reg, out);
}